// round 9
// baseline (speedup 1.0000x reference)
#include <cuda_runtime.h>

// ---------------------------------------------------------------------------
// Problem constants
// ---------------------------------------------------------------------------
constexpr int TFR   = 65536;
constexpr int KB9   = 9;
constexpr int BATCH = 32;
constexpr int LOUT  = (TFR - 1) * 4;            // 262140

constexpr int OT   = 1000;                      // output samples per tile
constexpr int NT   = (LOUT + OT - 1) / OT;      // 263 tiles
constexpr int NTHR = 256;

// Shared layout (word offsets), linear rows; strides 12/4/20 are
// conflict-free for .128 access with consecutive-row-per-lane patterns.
constexpr int OFF_MAG = 0;                       // mag rows: 260 x 12
constexpr int OFF_WAV = 3120;                    // wav groups: 256 x 4
constexpr int OFF_P   = 4144;                    // P rows: 253 x 20
constexpr int SMWORDS = 4144 + 253 * 20;         // 9204 words = 36816 B

// ---------------------------------------------------------------------------
// Compile-time twiddles (all angles multiples of pi/8)
// ---------------------------------------------------------------------------
#define HD __host__ __device__ __forceinline__

HD constexpr float cos8c(int m) {
    m &= 15;
    const int mm = m & 7;
    const float v =
        (mm == 0) ?  1.0f :
        (mm == 1) ?  0.92387953251128674f :
        (mm == 2) ?  0.70710678118654752f :
        (mm == 3) ?  0.38268343236508977f :
        (mm == 4) ?  0.0f :
        (mm == 5) ? -0.38268343236508977f :
        (mm == 6) ? -0.70710678118654752f :
                    -0.92387953251128674f;
    return (m & 8) ? -v : v;
}
HD constexpr float sin8c(int m) { return cos8c(m + 12); }
HD constexpr float wwinc(int n) { return 0.5f - 0.5f * cos8c(n); }   // hann(16)
HD constexpr float CSc(int k, int n) { return ((k == 0) ? 1.0f : 2.0f) * 0.0625f * cos8c(k * n) * wwinc(n); }
HD constexpr float envsum(int r) {
    return wwinc(r)      * wwinc(r)      + wwinc(r + 4)  * wwinc(r + 4)
         + wwinc(r + 8)  * wwinc(r + 8)  + wwinc(r + 12) * wwinc(r + 12);
}
HD constexpr float EINVc(int r) { return 1.0f / envsum(r); }
HD constexpr float CSF(int k, int n) { return CSc(k, n) * EINVc(n & 3); }
HD constexpr float W8c(int n) { return wwinc(n) * 0.125f; }          // window/8 for P rows

// Runtime tables for rare edge-fallback paths
__constant__ float C8T[16] = { cos8c(0), cos8c(1), cos8c(2), cos8c(3), cos8c(4), cos8c(5), cos8c(6), cos8c(7),
                               cos8c(8), cos8c(9), cos8c(10), cos8c(11), cos8c(12), cos8c(13), cos8c(14), cos8c(15) };
__constant__ float W16T[16] = { wwinc(0), wwinc(1), wwinc(2), wwinc(3), wwinc(4), wwinc(5), wwinc(6), wwinc(7),
                                wwinc(8), wwinc(9), wwinc(10), wwinc(11), wwinc(12), wwinc(13), wwinc(14), wwinc(15) };

// ---------------------------------------------------------------------------
// Phase-A accumulator (env folded in; fully constant-folded)
// ---------------------------------------------------------------------------
template<int JJ>
__device__ __forceinline__ void accA(const float4 u0, const float4 u1, const float m4,
                                     float& y0, float& y1, float& y2, float& y3)
{
    { constexpr int n = 4 * JJ + 0;
      if (CSF(0,n) != 0.f) y0 = fmaf(u0.x, CSF(0,n), y0);
      if (CSF(1,n) != 0.f) y0 = fmaf(u0.y, CSF(1,n), y0);
      if (CSF(2,n) != 0.f) y0 = fmaf(u0.z, CSF(2,n), y0);
      if (CSF(3,n) != 0.f) y0 = fmaf(u0.w, CSF(3,n), y0);
      if (CSF(4,n) != 0.f) y0 = fmaf(m4,   CSF(4,n), y0); }
    { constexpr int n = 4 * JJ + 1;
      if (CSF(0,n) != 0.f) y1 = fmaf(u1.x, CSF(0,n), y1);
      if (CSF(1,n) != 0.f) y1 = fmaf(u1.y, CSF(1,n), y1);
      if (CSF(2,n) != 0.f) y1 = fmaf(u1.z, CSF(2,n), y1);
      if (CSF(3,n) != 0.f) y1 = fmaf(u1.w, CSF(3,n), y1); }
    { constexpr int n = 4 * JJ + 2;
      if (CSF(0,n) != 0.f) y2 = fmaf(u0.x, CSF(0,n), y2);
      if (CSF(1,n) != 0.f) y2 = fmaf(u0.y, CSF(1,n), y2);
      if (CSF(2,n) != 0.f) y2 = fmaf(u0.z, CSF(2,n), y2);
      if (CSF(3,n) != 0.f) y2 = fmaf(u0.w, CSF(3,n), y2);
      if (CSF(4,n) != 0.f) y2 = fmaf(m4,   CSF(4,n), y2); }
    { constexpr int n = 4 * JJ + 3;
      if (CSF(0,n) != 0.f) y3 = fmaf(u1.x, CSF(0,n), y3);
      if (CSF(1,n) != 0.f) y3 = fmaf(u1.y, CSF(1,n), y3);
      if (CSF(2,n) != 0.f) y3 = fmaf(u1.z, CSF(2,n), y3);
      if (CSF(3,n) != 0.f) y3 = fmaf(u1.w, CSF(3,n), y3); }
}

// ---------------------------------------------------------------------------
// B1 frame processing, FFT-folded; results returned in registers.
// ---------------------------------------------------------------------------
__device__ __forceinline__ void processFrame(const float4 A0, const float4 A1,
                                             const float4 A2, const float4 A3,
                                             const float* __restrict__ mrp,
                                             float4& R0, float4& R1, float4& R2, float4& R3)
{
    constexpr float c1 = 0.92387953251128674f;   // cos(pi/8)
    constexpr float c2 = 0.70710678118654752f;   // cos(pi/4)
    constexpr float c3 = 0.38268343236508977f;   // cos(3pi/8)

    const float x8 = A2.x;
    const float e1 = wwinc(1) * (A0.y + A3.w), o1 = wwinc(1) * (A0.y - A3.w);
    const float e2 = wwinc(2) * (A0.z + A3.z), o2 = wwinc(2) * (A0.z - A3.z);
    const float e3 = wwinc(3) * (A0.w + A3.y), o3 = wwinc(3) * (A0.w - A3.y);
    const float e4 = wwinc(4) * (A1.x + A3.x), o4 = wwinc(4) * (A1.x - A3.x);
    const float e5 = wwinc(5) * (A1.y + A2.w), o5 = wwinc(5) * (A1.y - A2.w);
    const float e6 = wwinc(6) * (A1.z + A2.z), o6 = wwinc(6) * (A1.z - A2.z);
    const float e7 = wwinc(7) * (A1.w + A2.y), o7 = wwinc(7) * (A1.w - A2.y);

    const float es1 = e1 + e7, es2 = e2 + e6, es3 = e3 + e5;
    const float ed1 = e1 - e7, ed2 = e2 - e6, ed3 = e3 - e5;
    const float os1 = o1 + o7, os2 = o2 + o6, os3 = o3 + o5;
    const float od1 = o1 - o7, od2 = o2 - o6, od3 = o3 - o5;

    float re[9], im[9];
    {   const float t1 = c2 * (es1 - es3);
        const float t2 = x8 - e4, t3 = x8 + e4;
        const float q  = es1 + es3;
        const float Aa = t3 + es2;
        re[0] = Aa + q;  re[8] = Aa - q;
        re[2] = t2 + t1; re[6] = t2 - t1;
        re[4] = t3 - es2; }
    {   const float m  = ed2 * c2;
        const float v  = m - x8, w = -m - x8;
        const float u  = fmaf(ed1, c1,  ed3 * c3);
        const float u2 = fmaf(ed1, c3, -(ed3 * c1));
        re[1] = v + u;  re[7] = v - u;
        re[3] = w + u2; re[5] = w - u2; }
    {   const float a  = fmaf(os1, c3,  os3 * c1);
        const float b  = fmaf(os2, c2,  o4);
        const float a2 = fmaf(os1, c1, -(os3 * c3));
        const float b2 = fmaf(os2, c2, -o4);
        im[1] = -(a + b);   im[3] = -(a2 + b2);
        im[5] = b2 - a2;    im[7] = b - a; }
    {   const float t4 = c2 * (od1 + od3);
        im[2] = -(t4 + od2); im[6] = od2 - t4; im[4] = od3 - od1; }

    const float4 MS = *reinterpret_cast<const float4*>(mrp);
    const float4 MD = *reinterpret_cast<const float4*>(mrp + 4);
    float mv[9];
    mv[0] = 0.5f * (MS.x + MD.x);  mv[8] = 0.5f * (MS.x - MD.x);
    mv[1] = 0.5f * (MS.y + MD.y);  mv[7] = 0.5f * (MS.y - MD.y);
    mv[2] = 0.5f * (MS.z + MD.z);  mv[6] = 0.5f * (MS.z - MD.z);
    mv[3] = 0.5f * (MS.w + MD.w);  mv[5] = 0.5f * (MS.w - MD.w);
    mv[4] = mrp[8];

    float ca[9], sa[9];
    ca[0] = copysignf(mv[0], re[0]);
    ca[8] = copysignf(mv[8], re[8]);
    #pragma unroll
    for (int k = 1; k < 8; k++) {
        const float n2 = fmaf(re[k], re[k], im[k] * im[k]);
        if (n2 > 0.f) {
            const float u = mv[k] * rsqrtf(n2);
            ca[k] = re[k] * u;
            sa[k] = im[k] * u;
        } else {
            ca[k] = mv[k];
            sa[k] = 0.f;
        }
    }

    const float Ai1 = ca[1] + ca[7], Ai2 = ca[2] + ca[6], Ai3 = ca[3] + ca[5];
    const float Ci1 = ca[1] - ca[7], Ci2 = ca[2] - ca[6], Ci3 = ca[3] - ca[5];
    const float Si1 = sa[1] + sa[7], Si2 = sa[2] + sa[6], Si3 = sa[3] + sa[5];
    const float Di1 = sa[1] - sa[7], Di2 = sa[2] - sa[6], Di3 = sa[3] - sa[5];
    const float z2  = 0.5f * (ca[0] + ca[8]);
    const float z2p = 0.5f * (ca[0] - ca[8]);
    const float ca4 = ca[4], sa4 = sa[4];

    const float h1 = c2 * (Ai1 - Ai3);
    const float h2 = c2 * (Di1 + Di3);
    const float za = z2 - ca4, zb = z2 + ca4;
    const float E2 = za + h1, E6 = za - h1, E4 = zb - Ai2;
    const float O2 = h2 + Di2, O6 = h2 - Di2, O4 = Di1 - Di3;
    const float s8  = (zb + Ai2) - (Ai1 + Ai3);
    const float s2  = E2 - O2, s14 = E2 + O2;
    const float s4  = E4 - O4, s12 = E4 + O4;
    const float s6  = E6 - O6, s10 = E6 + O6;

    const float mC  = Ci2 * c2;
    const float uE  = fmaf(Ci1, c1,  Ci3 * c3);
    const float u2E = fmaf(Ci1, c3, -(Ci3 * c1));
    const float ta  = z2p + mC, tb = z2p - mC;
    const float E1 = ta + uE, E7 = ta - uE, E3 = tb + u2E, E5 = tb - u2E;
    const float nS  = Si2 * c2;
    const float vO  = fmaf(Si1, c3,  Si3 * c1);
    const float v2O = fmaf(Si1, c1, -(Si3 * c3));
    const float wo = nS + sa4, w2o = nS - sa4;
    const float O1 = vO + wo, O7 = vO - wo, O3 = v2O + w2o, O5 = v2O - w2o;
    const float s1  = E1 - O1, s15 = E1 + O1;
    const float s3  = E3 - O3, s13 = E3 + O3;
    const float s5  = E5 - O5, s11 = E5 + O5;
    const float s7  = E7 - O7, s9  = E7 + O7;

    R0 = make_float4(0.f,         W8c(1)*s1,   W8c(2)*s2,   W8c(3)*s3);
    R1 = make_float4(W8c(4)*s4,   W8c(5)*s5,   W8c(6)*s6,   W8c(7)*s7);
    R2 = make_float4(W8c(8)*s8,   W8c(9)*s9,   W8c(10)*s10, W8c(11)*s11);
    R3 = make_float4(W8c(12)*s12, W8c(13)*s13, W8c(14)*s14, W8c(15)*s15);
}

// ---------------------------------------------------------------------------
__global__ void __launch_bounds__(NTHR, 6)
glim_kernel(const float* __restrict__ mag, float* __restrict__ out)
{
    __shared__ __align__(16) float sm[SMWORDS];

    const int tid  = threadIdx.x;
    const int lane = tid & 31;
    const int b    = blockIdx.y;
    const int s0   = blockIdx.x * OT;
    const int nout = min(OT, LOUT - s0);
    const int F0   = s0 >> 2;
    const int TLO  = max(0, F0 - 1);
    const int THI  = min(TFR - 1, (s0 + nout + 7) >> 2);
    const int NFR  = THI - TLO + 1;
    const int tM0  = TLO - 3;
    const int ROWS = NFR + 7;
    const bool interiorTile = (blockIdx.x > 0) && (blockIdx.x < NT - 1);

    const float* magb = mag + (size_t)b * (KB9 * TFR);

    // ---- stage: load bin pairs, store combined S/D + M4 ----
    #pragma unroll
    for (int pass = 0; pass < 2; pass++) {
        const int tt = tid + pass * NTHR;
        if (tt < ROWS) {
            const int tg = tM0 + tt;
            float4 S, D; float m4;
            if (tg >= 0 && tg < TFR) {
                const float* gp = magb + tg;
                const float a0 = __ldg(gp);            const float a8 = __ldg(gp + 8 * TFR);
                const float a1 = __ldg(gp + 1 * TFR);  const float a7 = __ldg(gp + 7 * TFR);
                const float a2 = __ldg(gp + 2 * TFR);  const float a6 = __ldg(gp + 6 * TFR);
                const float a3 = __ldg(gp + 3 * TFR);  const float a5 = __ldg(gp + 5 * TFR);
                m4 = __ldg(gp + 4 * TFR);
                S = make_float4(a0 + a8, a1 + a7, a2 + a6, a3 + a5);
                D = make_float4(a0 - a8, a1 - a7, a2 - a6, a3 - a5);
            } else {
                S = make_float4(0.f, 0.f, 0.f, 0.f);
                D = S; m4 = 0.f;
            }
            float* rp = sm + OFF_MAG + tt * 12;
            *reinterpret_cast<float4*>(rp)     = S;
            *reinterpret_cast<float4*>(rp + 4) = D;
            rp[8] = m4;
        }
    }
    __syncthreads();

    // ---- Phase A: wav_i group in registers ----
    const int ngA = NFR + 3;
    float ay0 = 0.f, ay1 = 0.f, ay2 = 0.f, ay3 = 0.f;
    if (tid < ngA) {
        const int g     = tid;
        const int jbase = 4 * TLO - 8 + 4 * g;
        const int X     = TLO + g;
        if (jbase >= 0 && jbase + 3 < LOUT && X >= 3 && X <= TFR - 1) {
            const float* r0 = sm + OFF_MAG + g * 12;
            {   const float4 u0 = *reinterpret_cast<const float4*>(r0);
                const float4 u1 = *reinterpret_cast<const float4*>(r0 + 4);
                accA<3>(u0, u1, r0[8], ay0, ay1, ay2, ay3); }
            {   const float4 u0 = *reinterpret_cast<const float4*>(r0 + 12);
                const float4 u1 = *reinterpret_cast<const float4*>(r0 + 16);
                accA<2>(u0, u1, r0[20], ay0, ay1, ay2, ay3); }
            {   const float4 u0 = *reinterpret_cast<const float4*>(r0 + 24);
                const float4 u1 = *reinterpret_cast<const float4*>(r0 + 28);
                accA<1>(u0, u1, r0[32], ay0, ay1, ay2, ay3); }
            {   const float4 u0 = *reinterpret_cast<const float4*>(r0 + 36);
                const float4 u1 = *reinterpret_cast<const float4*>(r0 + 40);
                accA<0>(u0, u1, r0[44], ay0, ay1, ay2, ay3); }
        } else {
            // Edge fallback: reflect + clamp + edge env (runtime tables)
            float yv[4];
            for (int r = 0; r < 4; r++) {
                const int jg = jbase + r;
                const int jr = (jg < 0) ? -jg : ((jg >= LOUT) ? 2 * LOUT - 2 - jg : jg);
                const int p  = jr + 8;
                const int Xp = p >> 2;
                const int rr = p & 3;
                float acc = 0.f, env = 0.f;
                for (int jj = 0; jj < 4; jj++) {
                    const int tt = Xp - jj;
                    if (tt < 0 || tt >= TFR) continue;
                    const int n = rr + 4 * jj;
                    const float w = W16T[n];
                    const float* rp = sm + OFF_MAG + (tt - tM0) * 12;
                    float ssum;
                    if (n & 1) {
                        ssum = rp[4]
                             + 2.f * (rp[5] * C8T[n & 15] + rp[6] * C8T[(2 * n) & 15] + rp[7] * C8T[(3 * n) & 15]);
                    } else {
                        ssum = rp[0]
                             + 2.f * (rp[1] * C8T[n & 15] + rp[2] * C8T[(2 * n) & 15] + rp[3] * C8T[(3 * n) & 15]
                                    + rp[8] * C8T[(4 * n) & 15]);
                    }
                    acc = fmaf(ssum, 0.0625f * w, acc);
                    env = fmaf(w, w, env);
                }
                yv[r] = acc / env;
            }
            ay0 = yv[0]; ay1 = yv[1]; ay2 = yv[2]; ay3 = yv[3];
        }
    }

    // Seam groups to smem (only next-warp lanes 0..2 are ever read from smem)
    if (tid < ngA && lane <= 2) {
        *reinterpret_cast<float4*>(sm + OFF_WAV + tid * 4) = make_float4(ay0, ay1, ay2, ay3);
    }

    // Register exchange: groups f+1..f+3 (valid for lane+d <= 31)
    float x4  = __shfl_down_sync(0xFFFFFFFFu, ay0, 1);
    float x5  = __shfl_down_sync(0xFFFFFFFFu, ay1, 1);
    float x6  = __shfl_down_sync(0xFFFFFFFFu, ay2, 1);
    float x7  = __shfl_down_sync(0xFFFFFFFFu, ay3, 1);
    float x8  = __shfl_down_sync(0xFFFFFFFFu, ay0, 2);
    float x9  = __shfl_down_sync(0xFFFFFFFFu, ay1, 2);
    float x10 = __shfl_down_sync(0xFFFFFFFFu, ay2, 2);
    float x11 = __shfl_down_sync(0xFFFFFFFFu, ay3, 2);
    float x12 = __shfl_down_sync(0xFFFFFFFFu, ay0, 3);
    float x13 = __shfl_down_sync(0xFFFFFFFFu, ay1, 3);
    float x14 = __shfl_down_sync(0xFFFFFFFFu, ay2, 3);
    float x15 = __shfl_down_sync(0xFFFFFFFFu, ay3, 3);

    __syncthreads();

    // ---- Phase B1: boundary patch + frame processing (P row in registers) ----
    float4 P0 = make_float4(0.f, 0.f, 0.f, 0.f);
    float4 P1 = P0, P2 = P0, P3 = P0;
    if (tid < NFR) {
        const int f = tid;
        if (lane >= 29) {
            if (lane == 31) {
                const float4 w = *reinterpret_cast<const float4*>(sm + OFF_WAV + (f + 1) * 4);
                x4 = w.x; x5 = w.y; x6 = w.z; x7 = w.w;
            }
            if (lane >= 30) {
                const float4 w = *reinterpret_cast<const float4*>(sm + OFF_WAV + (f + 2) * 4);
                x8 = w.x; x9 = w.y; x10 = w.z; x11 = w.w;
            }
            {
                const float4 w = *reinterpret_cast<const float4*>(sm + OFF_WAV + (f + 3) * 4);
                x12 = w.x; x13 = w.y; x14 = w.z; x15 = w.w;
            }
        }
        processFrame(make_float4(ay0, ay1, ay2, ay3),
                     make_float4(x4, x5, x6, x7),
                     make_float4(x8, x9, x10, x11),
                     make_float4(x12, x13, x14, x15),
                     sm + OFF_MAG + (f + 3) * 12,
                     P0, P1, P2, P3);
        // Store P rows only where smem is actually read
        if (lane <= 2 || lane >= 29 || !interiorTile) {
            float* prow = sm + OFF_P + f * 20;
            *reinterpret_cast<float4*>(prow)      = P0;
            *reinterpret_cast<float4*>(prow + 4)  = P1;
            *reinterpret_cast<float4*>(prow + 8)  = P2;
            *reinterpret_cast<float4*>(prow + 12) = P3;
        }
    }

    // Register exchange for overlap-add: own P3 + chunks from g+1..g+3
    float4 ys;
    {
        const float t1x = __shfl_down_sync(0xFFFFFFFFu, P2.x, 1);
        const float t1y = __shfl_down_sync(0xFFFFFFFFu, P2.y, 1);
        const float t1z = __shfl_down_sync(0xFFFFFFFFu, P2.z, 1);
        const float t1w = __shfl_down_sync(0xFFFFFFFFu, P2.w, 1);
        const float t2x = __shfl_down_sync(0xFFFFFFFFu, P1.x, 2);
        const float t2y = __shfl_down_sync(0xFFFFFFFFu, P1.y, 2);
        const float t2z = __shfl_down_sync(0xFFFFFFFFu, P1.z, 2);
        const float t2w = __shfl_down_sync(0xFFFFFFFFu, P1.w, 2);
        const float t3x = __shfl_down_sync(0xFFFFFFFFu, P0.x, 3);
        const float t3y = __shfl_down_sync(0xFFFFFFFFu, P0.y, 3);
        const float t3z = __shfl_down_sync(0xFFFFFFFFu, P0.z, 3);
        const float t3w = __shfl_down_sync(0xFFFFFFFFu, P0.w, 3);
        ys.x = (P3.x + t1x) + (t2x + t3x);
        ys.y = (P3.y + t1y) + (t2y + t3y);
        ys.z = (P3.z + t1z) + (t2z + t3z);
        ys.w = (P3.w + t1w) + (t2w + t3w);
    }

    __syncthreads();

    // ---- Phase B2: overlap-add + env normalization ----
    const int ngO = nout >> 2;
    float* outb = out + (size_t)b * LOUT + s0;
    if (tid < ngO) {
        const int g = tid;
        if (interiorTile && lane < 29) {
            // shuffle path: ys already = P[g][12:]+P[g+1][8:]+P[g+2][4:]+P[g+3][0:]
            *reinterpret_cast<float4*>(outb + 4 * g) =
                make_float4(ys.x * EINVc(0), ys.y * EINVc(1), ys.z * EINVc(2), ys.w * EINVc(3));
        } else if (interiorTile) {
            // seam lanes: rows g..g+3 from smem (all stored by predicate)
            const float* r0 = sm + OFF_P + g * 20;
            const float4 q3 = *reinterpret_cast<const float4*>(r0 + 12);
            const float4 q2 = *reinterpret_cast<const float4*>(r0 + 20 + 8);
            const float4 q1 = *reinterpret_cast<const float4*>(r0 + 40 + 4);
            const float4 q0 = *reinterpret_cast<const float4*>(r0 + 60);
            *reinterpret_cast<float4*>(outb + 4 * g) = make_float4(
                ((q0.x + q1.x) + (q2.x + q3.x)) * EINVc(0),
                ((q0.y + q1.y) + (q2.y + q3.y)) * EINVc(1),
                ((q0.z + q1.z) + (q2.z + q3.z)) * EINVc(2),
                ((q0.w + q1.w) + (q2.w + q3.w)) * EINVc(3));
        } else {
            // edge tiles: original general path (all P rows are in smem)
            const int X = F0 + g + 2;
            if (X - 3 >= TLO && X <= THI) {
                const int Rb = X - TLO - 3;
                const float* r0 = sm + OFF_P + Rb * 20;
                const float4 q3 = *reinterpret_cast<const float4*>(r0 + 12);
                const float4 q2 = *reinterpret_cast<const float4*>(r0 + 20 + 8);
                const float4 q1 = *reinterpret_cast<const float4*>(r0 + 40 + 4);
                const float4 q0 = *reinterpret_cast<const float4*>(r0 + 60);
                *reinterpret_cast<float4*>(outb + 4 * g) = make_float4(
                    ((q0.x + q1.x) + (q2.x + q3.x)) * EINVc(0),
                    ((q0.y + q1.y) + (q2.y + q3.y)) * EINVc(1),
                    ((q0.z + q1.z) + (q2.z + q3.z)) * EINVc(2),
                    ((q0.w + q1.w) + (q2.w + q3.w)) * EINVc(3));
            } else {
                for (int r = 0; r < 4; r++) {
                    const int s  = s0 + 4 * g + r;
                    const int p  = s + 8;
                    const int Xp = p >> 2;
                    const int rr = p & 3;
                    float acc = 0.f, env = 0.f;
                    for (int jj = 0; jj < 4; jj++) {
                        const int tt = Xp - jj;
                        if (tt < TLO || tt > THI) continue;
                        const int n = rr + 4 * jj;
                        const float w = W16T[n];
                        acc += sm[OFF_P + (tt - TLO) * 20 + n];
                        env = fmaf(w, w, env);
                    }
                    outb[4 * g + r] = acc / env;
                }
            }
        }
    }
}

// ---------------------------------------------------------------------------
extern "C" void kernel_launch(void* const* d_in, const int* in_sizes, int n_in,
                              void* d_out, int out_size)
{
    (void)in_sizes; (void)n_in; (void)out_size;
    const float* mag = (const float*)d_in[0];
    float* out = (float*)d_out;
    // Maximize shared carveout so 6 CTAs/SM (36.8 KB each) stay resident.
    cudaFuncSetAttribute(glim_kernel, cudaFuncAttributePreferredSharedMemoryCarveout, 100);
    dim3 grid(NT, BATCH);
    glim_kernel<<<grid, NTHR>>>(mag, out);
}

// round 10
// speedup vs baseline: 1.0293x; 1.0293x over previous
#include <cuda_runtime.h>

// ---------------------------------------------------------------------------
// Problem constants
// ---------------------------------------------------------------------------
constexpr int TFR   = 65536;
constexpr int KB9   = 9;
constexpr int BATCH = 32;
constexpr int LOUT  = (TFR - 1) * 4;            // 262140

constexpr int OT   = 1000;                      // output samples per tile
constexpr int NT   = (LOUT + OT - 1) / OT;      // 263 tiles
constexpr int NTHR = 256;

// ---- interior-kernel plane layout (word offsets; all strides 4 -> conflict-free)
constexpr int I_OFF_S   = 0;                     // S plane: 260 x 4
constexpr int I_OFF_D   = 1040;                  // D plane: 260 x 4
constexpr int I_OFF_M4  = 2080;                  // m4 plane: 260
constexpr int I_OFF_WAV = 2340;                  // wav plane: 256 x 4
constexpr int I_OFF_P0  = 3364;                  // P chunk planes: 253 x 4 each
constexpr int I_OFF_P1  = 4376;
constexpr int I_OFF_P2  = 5388;
constexpr int I_OFF_P3  = 6400;
constexpr int I_SMW     = 7412;                  // 29648 bytes

// ---- edge-kernel layout (R6 linear rows, strides 12/4/20)
constexpr int E_OFF_MAG = 0;                     // 260 x 12
constexpr int E_OFF_WAV = 3120;                  // 256 x 4
constexpr int E_OFF_P   = 4144;                  // 253 x 20
constexpr int E_SMW     = 4144 + 253 * 20;       // 9204 words

// ---------------------------------------------------------------------------
// Compile-time twiddles (all angles multiples of pi/8)
// ---------------------------------------------------------------------------
#define HD __host__ __device__ __forceinline__

HD constexpr float cos8c(int m) {
    m &= 15;
    const int mm = m & 7;
    const float v =
        (mm == 0) ?  1.0f :
        (mm == 1) ?  0.92387953251128674f :
        (mm == 2) ?  0.70710678118654752f :
        (mm == 3) ?  0.38268343236508977f :
        (mm == 4) ?  0.0f :
        (mm == 5) ? -0.38268343236508977f :
        (mm == 6) ? -0.70710678118654752f :
                    -0.92387953251128674f;
    return (m & 8) ? -v : v;
}
HD constexpr float sin8c(int m) { return cos8c(m + 12); }
HD constexpr float wwinc(int n) { return 0.5f - 0.5f * cos8c(n); }   // hann(16)
HD constexpr float CSc(int k, int n) { return ((k == 0) ? 1.0f : 2.0f) * 0.0625f * cos8c(k * n) * wwinc(n); }
HD constexpr float envsum(int r) {
    return wwinc(r)      * wwinc(r)      + wwinc(r + 4)  * wwinc(r + 4)
         + wwinc(r + 8)  * wwinc(r + 8)  + wwinc(r + 12) * wwinc(r + 12);
}
HD constexpr float EINVc(int r) { return 1.0f / envsum(r); }
HD constexpr float CSF(int k, int n) { return CSc(k, n) * EINVc(n & 3); }
HD constexpr float W8c(int n) { return wwinc(n) * 0.125f; }

// Runtime tables (edge kernel only)
__constant__ float C8T[16] = { cos8c(0), cos8c(1), cos8c(2), cos8c(3), cos8c(4), cos8c(5), cos8c(6), cos8c(7),
                               cos8c(8), cos8c(9), cos8c(10), cos8c(11), cos8c(12), cos8c(13), cos8c(14), cos8c(15) };
__constant__ float W16T[16] = { wwinc(0), wwinc(1), wwinc(2), wwinc(3), wwinc(4), wwinc(5), wwinc(6), wwinc(7),
                                wwinc(8), wwinc(9), wwinc(10), wwinc(11), wwinc(12), wwinc(13), wwinc(14), wwinc(15) };

// ---------------------------------------------------------------------------
// Phase-A accumulator (env folded in; fully constant-folded)
// ---------------------------------------------------------------------------
template<int JJ>
__device__ __forceinline__ void accA(const float4 u0, const float4 u1, const float m4,
                                     float& y0, float& y1, float& y2, float& y3)
{
    { constexpr int n = 4 * JJ + 0;
      if (CSF(0,n) != 0.f) y0 = fmaf(u0.x, CSF(0,n), y0);
      if (CSF(1,n) != 0.f) y0 = fmaf(u0.y, CSF(1,n), y0);
      if (CSF(2,n) != 0.f) y0 = fmaf(u0.z, CSF(2,n), y0);
      if (CSF(3,n) != 0.f) y0 = fmaf(u0.w, CSF(3,n), y0);
      if (CSF(4,n) != 0.f) y0 = fmaf(m4,   CSF(4,n), y0); }
    { constexpr int n = 4 * JJ + 1;
      if (CSF(0,n) != 0.f) y1 = fmaf(u1.x, CSF(0,n), y1);
      if (CSF(1,n) != 0.f) y1 = fmaf(u1.y, CSF(1,n), y1);
      if (CSF(2,n) != 0.f) y1 = fmaf(u1.z, CSF(2,n), y1);
      if (CSF(3,n) != 0.f) y1 = fmaf(u1.w, CSF(3,n), y1); }
    { constexpr int n = 4 * JJ + 2;
      if (CSF(0,n) != 0.f) y2 = fmaf(u0.x, CSF(0,n), y2);
      if (CSF(1,n) != 0.f) y2 = fmaf(u0.y, CSF(1,n), y2);
      if (CSF(2,n) != 0.f) y2 = fmaf(u0.z, CSF(2,n), y2);
      if (CSF(3,n) != 0.f) y2 = fmaf(u0.w, CSF(3,n), y2);
      if (CSF(4,n) != 0.f) y2 = fmaf(m4,   CSF(4,n), y2); }
    { constexpr int n = 4 * JJ + 3;
      if (CSF(0,n) != 0.f) y3 = fmaf(u1.x, CSF(0,n), y3);
      if (CSF(1,n) != 0.f) y3 = fmaf(u1.y, CSF(1,n), y3);
      if (CSF(2,n) != 0.f) y3 = fmaf(u1.z, CSF(2,n), y3);
      if (CSF(3,n) != 0.f) y3 = fmaf(u1.w, CSF(3,n), y3); }
}

// ---------------------------------------------------------------------------
// B1 frame processing, FFT-folded; result in registers.
// ---------------------------------------------------------------------------
__device__ __forceinline__ void processFrame(const float4 A0, const float4 A1,
                                             const float4 A2, const float4 A3,
                                             const float4 MS, const float4 MD, const float m4v,
                                             float4& R0, float4& R1, float4& R2, float4& R3)
{
    constexpr float c1 = 0.92387953251128674f;   // cos(pi/8)
    constexpr float c2 = 0.70710678118654752f;   // cos(pi/4)
    constexpr float c3 = 0.38268343236508977f;   // cos(3pi/8)

    const float x8 = A2.x;
    const float e1 = wwinc(1) * (A0.y + A3.w), o1 = wwinc(1) * (A0.y - A3.w);
    const float e2 = wwinc(2) * (A0.z + A3.z), o2 = wwinc(2) * (A0.z - A3.z);
    const float e3 = wwinc(3) * (A0.w + A3.y), o3 = wwinc(3) * (A0.w - A3.y);
    const float e4 = wwinc(4) * (A1.x + A3.x), o4 = wwinc(4) * (A1.x - A3.x);
    const float e5 = wwinc(5) * (A1.y + A2.w), o5 = wwinc(5) * (A1.y - A2.w);
    const float e6 = wwinc(6) * (A1.z + A2.z), o6 = wwinc(6) * (A1.z - A2.z);
    const float e7 = wwinc(7) * (A1.w + A2.y), o7 = wwinc(7) * (A1.w - A2.y);

    const float es1 = e1 + e7, es2 = e2 + e6, es3 = e3 + e5;
    const float ed1 = e1 - e7, ed2 = e2 - e6, ed3 = e3 - e5;
    const float os1 = o1 + o7, os2 = o2 + o6, os3 = o3 + o5;
    const float od1 = o1 - o7, od2 = o2 - o6, od3 = o3 - o5;

    float re[9], im[9];
    {   const float t1 = c2 * (es1 - es3);
        const float t2 = x8 - e4, t3 = x8 + e4;
        const float q  = es1 + es3;
        const float Aa = t3 + es2;
        re[0] = Aa + q;  re[8] = Aa - q;
        re[2] = t2 + t1; re[6] = t2 - t1;
        re[4] = t3 - es2; }
    {   const float m  = ed2 * c2;
        const float v  = m - x8, w = -m - x8;
        const float u  = fmaf(ed1, c1,  ed3 * c3);
        const float u2 = fmaf(ed1, c3, -(ed3 * c1));
        re[1] = v + u;  re[7] = v - u;
        re[3] = w + u2; re[5] = w - u2; }
    {   const float a  = fmaf(os1, c3,  os3 * c1);
        const float b  = fmaf(os2, c2,  o4);
        const float a2 = fmaf(os1, c1, -(os3 * c3));
        const float b2 = fmaf(os2, c2, -o4);
        im[1] = -(a + b);   im[3] = -(a2 + b2);
        im[5] = b2 - a2;    im[7] = b - a; }
    {   const float t4 = c2 * (od1 + od3);
        im[2] = -(t4 + od2); im[6] = od2 - t4; im[4] = od3 - od1; }

    float mv[9];
    mv[0] = 0.5f * (MS.x + MD.x);  mv[8] = 0.5f * (MS.x - MD.x);
    mv[1] = 0.5f * (MS.y + MD.y);  mv[7] = 0.5f * (MS.y - MD.y);
    mv[2] = 0.5f * (MS.z + MD.z);  mv[6] = 0.5f * (MS.z - MD.z);
    mv[3] = 0.5f * (MS.w + MD.w);  mv[5] = 0.5f * (MS.w - MD.w);
    mv[4] = m4v;

    float ca[9], sa[9];
    ca[0] = copysignf(mv[0], re[0]);
    ca[8] = copysignf(mv[8], re[8]);
    #pragma unroll
    for (int k = 1; k < 8; k++) {
        const float n2 = fmaf(re[k], re[k], im[k] * im[k]);
        if (n2 > 0.f) {
            const float u = mv[k] * rsqrtf(n2);
            ca[k] = re[k] * u;
            sa[k] = im[k] * u;
        } else {
            ca[k] = mv[k];
            sa[k] = 0.f;
        }
    }

    const float Ai1 = ca[1] + ca[7], Ai2 = ca[2] + ca[6], Ai3 = ca[3] + ca[5];
    const float Ci1 = ca[1] - ca[7], Ci2 = ca[2] - ca[6], Ci3 = ca[3] - ca[5];
    const float Si1 = sa[1] + sa[7], Si2 = sa[2] + sa[6], Si3 = sa[3] + sa[5];
    const float Di1 = sa[1] - sa[7], Di2 = sa[2] - sa[6], Di3 = sa[3] - sa[5];
    const float z2  = 0.5f * (ca[0] + ca[8]);
    const float z2p = 0.5f * (ca[0] - ca[8]);
    const float ca4 = ca[4], sa4 = sa[4];

    const float h1 = c2 * (Ai1 - Ai3);
    const float h2 = c2 * (Di1 + Di3);
    const float za = z2 - ca4, zb = z2 + ca4;
    const float E2 = za + h1, E6 = za - h1, E4 = zb - Ai2;
    const float O2 = h2 + Di2, O6 = h2 - Di2, O4 = Di1 - Di3;
    const float s8  = (zb + Ai2) - (Ai1 + Ai3);
    const float s2  = E2 - O2, s14 = E2 + O2;
    const float s4  = E4 - O4, s12 = E4 + O4;
    const float s6  = E6 - O6, s10 = E6 + O6;

    const float mC  = Ci2 * c2;
    const float uE  = fmaf(Ci1, c1,  Ci3 * c3);
    const float u2E = fmaf(Ci1, c3, -(Ci3 * c1));
    const float ta  = z2p + mC, tb = z2p - mC;
    const float E1 = ta + uE, E7 = ta - uE, E3 = tb + u2E, E5 = tb - u2E;
    const float nS  = Si2 * c2;
    const float vO  = fmaf(Si1, c3,  Si3 * c1);
    const float v2O = fmaf(Si1, c1, -(Si3 * c3));
    const float wo = nS + sa4, w2o = nS - sa4;
    const float O1 = vO + wo, O7 = vO - wo, O3 = v2O + w2o, O5 = v2O - w2o;
    const float s1  = E1 - O1, s15 = E1 + O1;
    const float s3  = E3 - O3, s13 = E3 + O3;
    const float s5  = E5 - O5, s11 = E5 + O5;
    const float s7  = E7 - O7, s9  = E7 + O7;

    R0 = make_float4(0.f,         W8c(1)*s1,   W8c(2)*s2,   W8c(3)*s3);
    R1 = make_float4(W8c(4)*s4,   W8c(5)*s5,   W8c(6)*s6,   W8c(7)*s7);
    R2 = make_float4(W8c(8)*s8,   W8c(9)*s9,   W8c(10)*s10, W8c(11)*s11);
    R3 = make_float4(W8c(12)*s12, W8c(13)*s13, W8c(14)*s14, W8c(15)*s15);
}

// ---------------------------------------------------------------------------
// INTERIOR kernel: tiles 1..NT-2. All geometry compile-time; no fallbacks.
// ---------------------------------------------------------------------------
__global__ void __launch_bounds__(NTHR, 7)
glim_interior(const float* __restrict__ mag, float* __restrict__ out)
{
    __shared__ __align__(16) float sm[I_SMW];

    const int tid = threadIdx.x;
    const int b   = blockIdx.y;
    const int s0  = (blockIdx.x + 1) * OT;         // tiles 1..NT-2
    const int F0  = s0 >> 2;
    const int tM0 = F0 - 4;                         // TLO - 3, TLO = F0-1
    // Interior constants: NFR = 253, ngA = 256, ngO = 250, ROWS = 260.

    const float* magb = mag + (size_t)b * (KB9 * TFR);

    // ---- stage: S/D/m4 planes (no bounds checks needed) ----
    #pragma unroll
    for (int pass = 0; pass < 2; pass++) {
        const int tt = tid + pass * NTHR;
        if (tt < 260) {
            const float* gp = magb + (tM0 + tt);
            const float a0 = __ldg(gp);            const float a8 = __ldg(gp + 8 * TFR);
            const float a1 = __ldg(gp + 1 * TFR);  const float a7 = __ldg(gp + 7 * TFR);
            const float a2 = __ldg(gp + 2 * TFR);  const float a6 = __ldg(gp + 6 * TFR);
            const float a3 = __ldg(gp + 3 * TFR);  const float a5 = __ldg(gp + 5 * TFR);
            *reinterpret_cast<float4*>(sm + I_OFF_S + tt * 4) =
                make_float4(a0 + a8, a1 + a7, a2 + a6, a3 + a5);
            *reinterpret_cast<float4*>(sm + I_OFF_D + tt * 4) =
                make_float4(a0 - a8, a1 - a7, a2 - a6, a3 - a5);
            sm[I_OFF_M4 + tt] = __ldg(gp + 4 * TFR);
        }
    }
    __syncthreads();

    // ---- Phase A: all 256 threads, pure fast path ----
    {
        const int g = tid;
        float y0 = 0.f, y1 = 0.f, y2 = 0.f, y3 = 0.f;
        #pragma unroll
        for (int d = 0; d < 4; d++) {
            const float4 u0 = *reinterpret_cast<const float4*>(sm + I_OFF_S + (g + d) * 4);
            const float4 u1 = *reinterpret_cast<const float4*>(sm + I_OFF_D + (g + d) * 4);
            const float  m4 = sm[I_OFF_M4 + g + d];
            switch (d) {
                case 0: accA<3>(u0, u1, m4, y0, y1, y2, y3); break;
                case 1: accA<2>(u0, u1, m4, y0, y1, y2, y3); break;
                case 2: accA<1>(u0, u1, m4, y0, y1, y2, y3); break;
                default: accA<0>(u0, u1, m4, y0, y1, y2, y3); break;
            }
        }
        *reinterpret_cast<float4*>(sm + I_OFF_WAV + g * 4) = make_float4(y0, y1, y2, y3);
    }
    __syncthreads();

    // ---- Phase B1: frames 0..252 ----
    if (tid < 253) {
        const int f = tid;
        const float4 A0 = *reinterpret_cast<const float4*>(sm + I_OFF_WAV + f * 4);
        const float4 A1 = *reinterpret_cast<const float4*>(sm + I_OFF_WAV + (f + 1) * 4);
        const float4 A2 = *reinterpret_cast<const float4*>(sm + I_OFF_WAV + (f + 2) * 4);
        const float4 A3 = *reinterpret_cast<const float4*>(sm + I_OFF_WAV + (f + 3) * 4);
        const float4 MS = *reinterpret_cast<const float4*>(sm + I_OFF_S + (f + 3) * 4);
        const float4 MD = *reinterpret_cast<const float4*>(sm + I_OFF_D + (f + 3) * 4);
        const float  m4 = sm[I_OFF_M4 + f + 3];
        float4 R0, R1, R2, R3;
        processFrame(A0, A1, A2, A3, MS, MD, m4, R0, R1, R2, R3);
        *reinterpret_cast<float4*>(sm + I_OFF_P0 + f * 4) = R0;
        *reinterpret_cast<float4*>(sm + I_OFF_P1 + f * 4) = R1;
        *reinterpret_cast<float4*>(sm + I_OFF_P2 + f * 4) = R2;
        *reinterpret_cast<float4*>(sm + I_OFF_P3 + f * 4) = R3;
    }
    __syncthreads();

    // ---- Phase B2: overlap-add, groups 0..249 ----
    if (tid < 250) {
        const int g = tid;
        const float4 q3 = *reinterpret_cast<const float4*>(sm + I_OFF_P3 + g * 4);
        const float4 q2 = *reinterpret_cast<const float4*>(sm + I_OFF_P2 + (g + 1) * 4);
        const float4 q1 = *reinterpret_cast<const float4*>(sm + I_OFF_P1 + (g + 2) * 4);
        const float4 q0 = *reinterpret_cast<const float4*>(sm + I_OFF_P0 + (g + 3) * 4);
        float* outb = out + (size_t)b * LOUT + s0;
        *reinterpret_cast<float4*>(outb + 4 * g) = make_float4(
            ((q0.x + q1.x) + (q2.x + q3.x)) * EINVc(0),
            ((q0.y + q1.y) + (q2.y + q3.y)) * EINVc(1),
            ((q0.z + q1.z) + (q2.z + q3.z)) * EINVc(2),
            ((q0.w + q1.w) + (q2.w + q3.w)) * EINVc(3));
    }
}

// ---------------------------------------------------------------------------
// EDGE kernel: tiles 0 and NT-1 (R6-proven logic, full fallbacks).
// ---------------------------------------------------------------------------
__global__ void __launch_bounds__(NTHR, 6)
glim_edge(const float* __restrict__ mag, float* __restrict__ out)
{
    __shared__ __align__(16) float sm[E_SMW];

    const int tid  = threadIdx.x;
    const int bx   = (blockIdx.x == 0) ? 0 : (NT - 1);
    const int b    = blockIdx.y;
    const int s0   = bx * OT;
    const int nout = min(OT, LOUT - s0);
    const int F0   = s0 >> 2;
    const int TLO  = max(0, F0 - 1);
    const int THI  = min(TFR - 1, (s0 + nout + 7) >> 2);
    const int NFR  = THI - TLO + 1;
    const int tM0  = TLO - 3;
    const int ROWS = NFR + 7;

    const float* magb = mag + (size_t)b * (KB9 * TFR);

    // ---- stage ----
    #pragma unroll
    for (int pass = 0; pass < 2; pass++) {
        const int tt = tid + pass * NTHR;
        if (tt < ROWS) {
            const int tg = tM0 + tt;
            float4 S, D; float m4;
            if (tg >= 0 && tg < TFR) {
                const float* gp = magb + tg;
                const float a0 = __ldg(gp);            const float a8 = __ldg(gp + 8 * TFR);
                const float a1 = __ldg(gp + 1 * TFR);  const float a7 = __ldg(gp + 7 * TFR);
                const float a2 = __ldg(gp + 2 * TFR);  const float a6 = __ldg(gp + 6 * TFR);
                const float a3 = __ldg(gp + 3 * TFR);  const float a5 = __ldg(gp + 5 * TFR);
                m4 = __ldg(gp + 4 * TFR);
                S = make_float4(a0 + a8, a1 + a7, a2 + a6, a3 + a5);
                D = make_float4(a0 - a8, a1 - a7, a2 - a6, a3 - a5);
            } else {
                S = make_float4(0.f, 0.f, 0.f, 0.f);
                D = S; m4 = 0.f;
            }
            float* rp = sm + E_OFF_MAG + tt * 12;
            *reinterpret_cast<float4*>(rp)     = S;
            *reinterpret_cast<float4*>(rp + 4) = D;
            rp[8] = m4;
        }
    }
    __syncthreads();

    // ---- Phase A ----
    const int ngA = NFR + 3;
    if (tid < ngA) {
        const int g     = tid;
        const int jbase = 4 * TLO - 8 + 4 * g;
        const int X     = TLO + g;
        if (jbase >= 0 && jbase + 3 < LOUT && X >= 3 && X <= TFR - 1) {
            float y0 = 0.f, y1 = 0.f, y2 = 0.f, y3 = 0.f;
            const float* r0 = sm + E_OFF_MAG + g * 12;
            {   accA<3>(*reinterpret_cast<const float4*>(r0),
                        *reinterpret_cast<const float4*>(r0 + 4), r0[8], y0, y1, y2, y3); }
            {   accA<2>(*reinterpret_cast<const float4*>(r0 + 12),
                        *reinterpret_cast<const float4*>(r0 + 16), r0[20], y0, y1, y2, y3); }
            {   accA<1>(*reinterpret_cast<const float4*>(r0 + 24),
                        *reinterpret_cast<const float4*>(r0 + 28), r0[32], y0, y1, y2, y3); }
            {   accA<0>(*reinterpret_cast<const float4*>(r0 + 36),
                        *reinterpret_cast<const float4*>(r0 + 40), r0[44], y0, y1, y2, y3); }
            *reinterpret_cast<float4*>(sm + E_OFF_WAV + g * 4) = make_float4(y0, y1, y2, y3);
        } else {
            float* wp = sm + E_OFF_WAV + g * 4;
            for (int r = 0; r < 4; r++) {
                const int jg = jbase + r;
                const int jr = (jg < 0) ? -jg : ((jg >= LOUT) ? 2 * LOUT - 2 - jg : jg);
                const int p  = jr + 8;
                const int Xp = p >> 2;
                const int rr = p & 3;
                float acc = 0.f, env = 0.f;
                for (int jj = 0; jj < 4; jj++) {
                    const int tt = Xp - jj;
                    if (tt < 0 || tt >= TFR) continue;
                    const int n = rr + 4 * jj;
                    const float w = W16T[n];
                    const float* rp = sm + E_OFF_MAG + (tt - tM0) * 12;
                    float ssum;
                    if (n & 1) {
                        ssum = rp[4]
                             + 2.f * (rp[5] * C8T[n & 15] + rp[6] * C8T[(2 * n) & 15] + rp[7] * C8T[(3 * n) & 15]);
                    } else {
                        ssum = rp[0]
                             + 2.f * (rp[1] * C8T[n & 15] + rp[2] * C8T[(2 * n) & 15] + rp[3] * C8T[(3 * n) & 15]
                                    + rp[8] * C8T[(4 * n) & 15]);
                    }
                    acc = fmaf(ssum, 0.0625f * w, acc);
                    env = fmaf(w, w, env);
                }
                wp[r] = acc / env;
            }
        }
    }
    __syncthreads();

    // ---- Phase B1 ----
    if (tid < NFR) {
        const int f = tid;
        const float4* w4 = reinterpret_cast<const float4*>(sm + E_OFF_WAV + f * 4);
        const float* mrp = sm + E_OFF_MAG + (f + 3) * 12;
        float4 R0, R1, R2, R3;
        processFrame(w4[0], w4[1], w4[2], w4[3],
                     *reinterpret_cast<const float4*>(mrp),
                     *reinterpret_cast<const float4*>(mrp + 4),
                     mrp[8], R0, R1, R2, R3);
        float* prow = sm + E_OFF_P + f * 20;
        *reinterpret_cast<float4*>(prow)      = R0;
        *reinterpret_cast<float4*>(prow + 4)  = R1;
        *reinterpret_cast<float4*>(prow + 8)  = R2;
        *reinterpret_cast<float4*>(prow + 12) = R3;
    }
    __syncthreads();

    // ---- Phase B2 ----
    const int ngO = (nout + 3) >> 2;
    float* outb = out + (size_t)b * LOUT + s0;
    if (tid < ngO) {
        const int g = tid;
        const int X = F0 + g + 2;
        const bool wholeGroup = (4 * g + 3 < nout);
        if (wholeGroup && X - 3 >= TLO && X <= THI) {
            const int Rb = X - TLO - 3;
            const float* r0 = sm + E_OFF_P + Rb * 20;
            const float4 q3 = *reinterpret_cast<const float4*>(r0 + 12);
            const float4 q2 = *reinterpret_cast<const float4*>(r0 + 20 + 8);
            const float4 q1 = *reinterpret_cast<const float4*>(r0 + 40 + 4);
            const float4 q0 = *reinterpret_cast<const float4*>(r0 + 60);
            *reinterpret_cast<float4*>(outb + 4 * g) = make_float4(
                ((q0.x + q1.x) + (q2.x + q3.x)) * EINVc(0),
                ((q0.y + q1.y) + (q2.y + q3.y)) * EINVc(1),
                ((q0.z + q1.z) + (q2.z + q3.z)) * EINVc(2),
                ((q0.w + q1.w) + (q2.w + q3.w)) * EINVc(3));
        } else {
            for (int r = 0; r < 4; r++) {
                const int so = 4 * g + r;
                if (so >= nout) break;
                const int s  = s0 + so;
                const int p  = s + 8;
                const int Xp = p >> 2;
                const int rr = p & 3;
                float acc = 0.f, env = 0.f;
                for (int jj = 0; jj < 4; jj++) {
                    const int tt = Xp - jj;
                    if (tt < TLO || tt > THI) continue;
                    const int n = rr + 4 * jj;
                    const float w = W16T[n];
                    acc += sm[E_OFF_P + (tt - TLO) * 20 + n];
                    env = fmaf(w, w, env);
                }
                outb[so] = acc / env;
            }
        }
    }
}

// ---------------------------------------------------------------------------
extern "C" void kernel_launch(void* const* d_in, const int* in_sizes, int n_in,
                              void* d_out, int out_size)
{
    (void)in_sizes; (void)n_in; (void)out_size;
    const float* mag = (const float*)d_in[0];
    float* out = (float*)d_out;
    cudaFuncSetAttribute(glim_interior, cudaFuncAttributePreferredSharedMemoryCarveout, 100);
    cudaFuncSetAttribute(glim_edge,     cudaFuncAttributePreferredSharedMemoryCarveout, 100);
    dim3 gridI(NT - 2, BATCH);
    glim_interior<<<gridI, NTHR>>>(mag, out);
    dim3 gridE(2, BATCH);
    glim_edge<<<gridE, NTHR>>>(mag, out);
}

// round 11
// speedup vs baseline: 1.1312x; 1.0990x over previous
#include <cuda_runtime.h>

// ---------------------------------------------------------------------------
// Problem constants
// ---------------------------------------------------------------------------
constexpr int TFR   = 65536;
constexpr int KB9   = 9;
constexpr int BATCH = 32;
constexpr int LOUT  = (TFR - 1) * 4;            // 262140

constexpr int OT   = 1000;                      // output samples per tile
constexpr int NT   = (LOUT + OT - 1) / OT;      // 263 tiles
constexpr int NTHR = 256;

// Plane layout (word offsets); every access is a stride-4 .128 -> conflict-free.
constexpr int I_OFF_S   = 0;                     // S plane: 260 x 4
constexpr int I_OFF_D   = 1040;                  // D plane: 260 x 4
constexpr int I_OFF_M4  = 2080;                  // m4 plane: 260
constexpr int I_OFF_WAV = 2340;                  // wav plane: 256 x 4
constexpr int I_OFF_P0  = 3364;                  // P chunk planes: 253 x 4 each
constexpr int I_OFF_P1  = 4376;
constexpr int I_OFF_P2  = 5388;
constexpr int I_OFF_P3  = 6400;
constexpr int I_SMW     = 7412;                  // 29648 bytes
constexpr int PPLANE    = 1012;                  // words per P plane

// ---------------------------------------------------------------------------
// Compile-time twiddles (all angles multiples of pi/8)
// ---------------------------------------------------------------------------
#define HD __host__ __device__ __forceinline__

HD constexpr float cos8c(int m) {
    m &= 15;
    const int mm = m & 7;
    const float v =
        (mm == 0) ?  1.0f :
        (mm == 1) ?  0.92387953251128674f :
        (mm == 2) ?  0.70710678118654752f :
        (mm == 3) ?  0.38268343236508977f :
        (mm == 4) ?  0.0f :
        (mm == 5) ? -0.38268343236508977f :
        (mm == 6) ? -0.70710678118654752f :
                    -0.92387953251128674f;
    return (m & 8) ? -v : v;
}
HD constexpr float sin8c(int m) { return cos8c(m + 12); }
HD constexpr float wwinc(int n) { return 0.5f - 0.5f * cos8c(n); }   // hann(16)
HD constexpr float CSc(int k, int n) { return ((k == 0) ? 1.0f : 2.0f) * 0.0625f * cos8c(k * n) * wwinc(n); }
HD constexpr float envsum(int r) {
    return wwinc(r)      * wwinc(r)      + wwinc(r + 4)  * wwinc(r + 4)
         + wwinc(r + 8)  * wwinc(r + 8)  + wwinc(r + 12) * wwinc(r + 12);
}
HD constexpr float EINVc(int r) { return 1.0f / envsum(r); }
HD constexpr float CSF(int k, int n) { return CSc(k, n) * EINVc(n & 3); }
HD constexpr float W8c(int n) { return wwinc(n) * 0.125f; }

// Runtime tables (edge fallbacks only)
__constant__ float C8T[16] = { cos8c(0), cos8c(1), cos8c(2), cos8c(3), cos8c(4), cos8c(5), cos8c(6), cos8c(7),
                               cos8c(8), cos8c(9), cos8c(10), cos8c(11), cos8c(12), cos8c(13), cos8c(14), cos8c(15) };
__constant__ float W16T[16] = { wwinc(0), wwinc(1), wwinc(2), wwinc(3), wwinc(4), wwinc(5), wwinc(6), wwinc(7),
                                wwinc(8), wwinc(9), wwinc(10), wwinc(11), wwinc(12), wwinc(13), wwinc(14), wwinc(15) };

// ---------------------------------------------------------------------------
// Phase-A accumulator (env folded in; fully constant-folded)
// ---------------------------------------------------------------------------
template<int JJ>
__device__ __forceinline__ void accA(const float4 u0, const float4 u1, const float m4,
                                     float& y0, float& y1, float& y2, float& y3)
{
    { constexpr int n = 4 * JJ + 0;
      if (CSF(0,n) != 0.f) y0 = fmaf(u0.x, CSF(0,n), y0);
      if (CSF(1,n) != 0.f) y0 = fmaf(u0.y, CSF(1,n), y0);
      if (CSF(2,n) != 0.f) y0 = fmaf(u0.z, CSF(2,n), y0);
      if (CSF(3,n) != 0.f) y0 = fmaf(u0.w, CSF(3,n), y0);
      if (CSF(4,n) != 0.f) y0 = fmaf(m4,   CSF(4,n), y0); }
    { constexpr int n = 4 * JJ + 1;
      if (CSF(0,n) != 0.f) y1 = fmaf(u1.x, CSF(0,n), y1);
      if (CSF(1,n) != 0.f) y1 = fmaf(u1.y, CSF(1,n), y1);
      if (CSF(2,n) != 0.f) y1 = fmaf(u1.z, CSF(2,n), y1);
      if (CSF(3,n) != 0.f) y1 = fmaf(u1.w, CSF(3,n), y1); }
    { constexpr int n = 4 * JJ + 2;
      if (CSF(0,n) != 0.f) y2 = fmaf(u0.x, CSF(0,n), y2);
      if (CSF(1,n) != 0.f) y2 = fmaf(u0.y, CSF(1,n), y2);
      if (CSF(2,n) != 0.f) y2 = fmaf(u0.z, CSF(2,n), y2);
      if (CSF(3,n) != 0.f) y2 = fmaf(u0.w, CSF(3,n), y2);
      if (CSF(4,n) != 0.f) y2 = fmaf(m4,   CSF(4,n), y2); }
    { constexpr int n = 4 * JJ + 3;
      if (CSF(0,n) != 0.f) y3 = fmaf(u1.x, CSF(0,n), y3);
      if (CSF(1,n) != 0.f) y3 = fmaf(u1.y, CSF(1,n), y3);
      if (CSF(2,n) != 0.f) y3 = fmaf(u1.z, CSF(2,n), y3);
      if (CSF(3,n) != 0.f) y3 = fmaf(u1.w, CSF(3,n), y3); }
}

// ---------------------------------------------------------------------------
// B1 frame processing, FFT-folded; result in registers.
// ---------------------------------------------------------------------------
__device__ __forceinline__ void processFrame(const float4 A0, const float4 A1,
                                             const float4 A2, const float4 A3,
                                             const float4 MS, const float4 MD, const float m4v,
                                             float4& R0, float4& R1, float4& R2, float4& R3)
{
    constexpr float c1 = 0.92387953251128674f;   // cos(pi/8)
    constexpr float c2 = 0.70710678118654752f;   // cos(pi/4)
    constexpr float c3 = 0.38268343236508977f;   // cos(3pi/8)

    const float x8 = A2.x;
    const float e1 = wwinc(1) * (A0.y + A3.w), o1 = wwinc(1) * (A0.y - A3.w);
    const float e2 = wwinc(2) * (A0.z + A3.z), o2 = wwinc(2) * (A0.z - A3.z);
    const float e3 = wwinc(3) * (A0.w + A3.y), o3 = wwinc(3) * (A0.w - A3.y);
    const float e4 = wwinc(4) * (A1.x + A3.x), o4 = wwinc(4) * (A1.x - A3.x);
    const float e5 = wwinc(5) * (A1.y + A2.w), o5 = wwinc(5) * (A1.y - A2.w);
    const float e6 = wwinc(6) * (A1.z + A2.z), o6 = wwinc(6) * (A1.z - A2.z);
    const float e7 = wwinc(7) * (A1.w + A2.y), o7 = wwinc(7) * (A1.w - A2.y);

    const float es1 = e1 + e7, es2 = e2 + e6, es3 = e3 + e5;
    const float ed1 = e1 - e7, ed2 = e2 - e6, ed3 = e3 - e5;
    const float os1 = o1 + o7, os2 = o2 + o6, os3 = o3 + o5;
    const float od1 = o1 - o7, od2 = o2 - o6, od3 = o3 - o5;

    float re[9], im[9];
    {   const float t1 = c2 * (es1 - es3);
        const float t2 = x8 - e4, t3 = x8 + e4;
        const float q  = es1 + es3;
        const float Aa = t3 + es2;
        re[0] = Aa + q;  re[8] = Aa - q;
        re[2] = t2 + t1; re[6] = t2 - t1;
        re[4] = t3 - es2; }
    {   const float m  = ed2 * c2;
        const float v  = m - x8, w = -m - x8;
        const float u  = fmaf(ed1, c1,  ed3 * c3);
        const float u2 = fmaf(ed1, c3, -(ed3 * c1));
        re[1] = v + u;  re[7] = v - u;
        re[3] = w + u2; re[5] = w - u2; }
    {   const float a  = fmaf(os1, c3,  os3 * c1);
        const float b  = fmaf(os2, c2,  o4);
        const float a2 = fmaf(os1, c1, -(os3 * c3));
        const float b2 = fmaf(os2, c2, -o4);
        im[1] = -(a + b);   im[3] = -(a2 + b2);
        im[5] = b2 - a2;    im[7] = b - a; }
    {   const float t4 = c2 * (od1 + od3);
        im[2] = -(t4 + od2); im[6] = od2 - t4; im[4] = od3 - od1; }

    float mv[9];
    mv[0] = 0.5f * (MS.x + MD.x);  mv[8] = 0.5f * (MS.x - MD.x);
    mv[1] = 0.5f * (MS.y + MD.y);  mv[7] = 0.5f * (MS.y - MD.y);
    mv[2] = 0.5f * (MS.z + MD.z);  mv[6] = 0.5f * (MS.z - MD.z);
    mv[3] = 0.5f * (MS.w + MD.w);  mv[5] = 0.5f * (MS.w - MD.w);
    mv[4] = m4v;

    float ca[9], sa[9];
    ca[0] = copysignf(mv[0], re[0]);
    ca[8] = copysignf(mv[8], re[8]);
    #pragma unroll
    for (int k = 1; k < 8; k++) {
        const float n2 = fmaf(re[k], re[k], im[k] * im[k]);
        if (n2 > 0.f) {
            const float u = mv[k] * rsqrtf(n2);
            ca[k] = re[k] * u;
            sa[k] = im[k] * u;
        } else {
            ca[k] = mv[k];
            sa[k] = 0.f;
        }
    }

    const float Ai1 = ca[1] + ca[7], Ai2 = ca[2] + ca[6], Ai3 = ca[3] + ca[5];
    const float Ci1 = ca[1] - ca[7], Ci2 = ca[2] - ca[6], Ci3 = ca[3] - ca[5];
    const float Si1 = sa[1] + sa[7], Si2 = sa[2] + sa[6], Si3 = sa[3] + sa[5];
    const float Di1 = sa[1] - sa[7], Di2 = sa[2] - sa[6], Di3 = sa[3] - sa[5];
    const float z2  = 0.5f * (ca[0] + ca[8]);
    const float z2p = 0.5f * (ca[0] - ca[8]);
    const float ca4 = ca[4], sa4 = sa[4];

    const float h1 = c2 * (Ai1 - Ai3);
    const float h2 = c2 * (Di1 + Di3);
    const float za = z2 - ca4, zb = z2 + ca4;
    const float E2 = za + h1, E6 = za - h1, E4 = zb - Ai2;
    const float O2 = h2 + Di2, O6 = h2 - Di2, O4 = Di1 - Di3;
    const float s8  = (zb + Ai2) - (Ai1 + Ai3);
    const float s2  = E2 - O2, s14 = E2 + O2;
    const float s4  = E4 - O4, s12 = E4 + O4;
    const float s6  = E6 - O6, s10 = E6 + O6;

    const float mC  = Ci2 * c2;
    const float uE  = fmaf(Ci1, c1,  Ci3 * c3);
    const float u2E = fmaf(Ci1, c3, -(Ci3 * c1));
    const float ta  = z2p + mC, tb = z2p - mC;
    const float E1 = ta + uE, E7 = ta - uE, E3 = tb + u2E, E5 = tb - u2E;
    const float nS  = Si2 * c2;
    const float vO  = fmaf(Si1, c3,  Si3 * c1);
    const float v2O = fmaf(Si1, c1, -(Si3 * c3));
    const float wo = nS + sa4, w2o = nS - sa4;
    const float O1 = vO + wo, O7 = vO - wo, O3 = v2O + w2o, O5 = v2O - w2o;
    const float s1  = E1 - O1, s15 = E1 + O1;
    const float s3  = E3 - O3, s13 = E3 + O3;
    const float s5  = E5 - O5, s11 = E5 + O5;
    const float s7  = E7 - O7, s9  = E7 + O7;

    R0 = make_float4(0.f,         W8c(1)*s1,   W8c(2)*s2,   W8c(3)*s3);
    R1 = make_float4(W8c(4)*s4,   W8c(5)*s5,   W8c(6)*s6,   W8c(7)*s7);
    R2 = make_float4(W8c(8)*s8,   W8c(9)*s9,   W8c(10)*s10, W8c(11)*s11);
    R3 = make_float4(W8c(12)*s12, W8c(13)*s13, W8c(14)*s14, W8c(15)*s15);
}

// ---------------------------------------------------------------------------
// Fused kernel: interior CTAs take the constant-geometry fast body; the 2
// edge tiles per batch row take the bounds-checked body. Branch is
// CTA-uniform, so the divergent __syncthreads are safe.
// ---------------------------------------------------------------------------
__global__ void __launch_bounds__(NTHR, 7)
glim_kernel(const float* __restrict__ mag, float* __restrict__ out)
{
    __shared__ __align__(16) float sm[I_SMW];

    const int tid = threadIdx.x;
    const int bx  = blockIdx.x;
    const int b   = blockIdx.y;
    const float* magb = mag + (size_t)b * (KB9 * TFR);

    if (bx > 0 && bx < NT - 1) {
        // ================= INTERIOR body (all geometry compile-time) =======
        const int s0  = bx * OT;
        const int F0  = s0 >> 2;
        const int tM0 = F0 - 4;                     // TLO - 3
        // constants: NFR = 253, ngA = 256, ngO = 250, ROWS = 260

        #pragma unroll
        for (int pass = 0; pass < 2; pass++) {
            const int tt = tid + pass * NTHR;
            if (tt < 260) {
                const float* gp = magb + (tM0 + tt);
                const float a0 = __ldg(gp);            const float a8 = __ldg(gp + 8 * TFR);
                const float a1 = __ldg(gp + 1 * TFR);  const float a7 = __ldg(gp + 7 * TFR);
                const float a2 = __ldg(gp + 2 * TFR);  const float a6 = __ldg(gp + 6 * TFR);
                const float a3 = __ldg(gp + 3 * TFR);  const float a5 = __ldg(gp + 5 * TFR);
                *reinterpret_cast<float4*>(sm + I_OFF_S + tt * 4) =
                    make_float4(a0 + a8, a1 + a7, a2 + a6, a3 + a5);
                *reinterpret_cast<float4*>(sm + I_OFF_D + tt * 4) =
                    make_float4(a0 - a8, a1 - a7, a2 - a6, a3 - a5);
                sm[I_OFF_M4 + tt] = __ldg(gp + 4 * TFR);
            }
        }
        __syncthreads();

        // Phase A: all 256 threads, pure fast path
        {
            const int g = tid;
            float y0 = 0.f, y1 = 0.f, y2 = 0.f, y3 = 0.f;
            {   const float4 u0 = *reinterpret_cast<const float4*>(sm + I_OFF_S + g * 4);
                const float4 u1 = *reinterpret_cast<const float4*>(sm + I_OFF_D + g * 4);
                accA<3>(u0, u1, sm[I_OFF_M4 + g], y0, y1, y2, y3); }
            {   const float4 u0 = *reinterpret_cast<const float4*>(sm + I_OFF_S + (g + 1) * 4);
                const float4 u1 = *reinterpret_cast<const float4*>(sm + I_OFF_D + (g + 1) * 4);
                accA<2>(u0, u1, sm[I_OFF_M4 + g + 1], y0, y1, y2, y3); }
            {   const float4 u0 = *reinterpret_cast<const float4*>(sm + I_OFF_S + (g + 2) * 4);
                const float4 u1 = *reinterpret_cast<const float4*>(sm + I_OFF_D + (g + 2) * 4);
                accA<1>(u0, u1, sm[I_OFF_M4 + g + 2], y0, y1, y2, y3); }
            {   const float4 u0 = *reinterpret_cast<const float4*>(sm + I_OFF_S + (g + 3) * 4);
                const float4 u1 = *reinterpret_cast<const float4*>(sm + I_OFF_D + (g + 3) * 4);
                accA<0>(u0, u1, sm[I_OFF_M4 + g + 3], y0, y1, y2, y3); }
            *reinterpret_cast<float4*>(sm + I_OFF_WAV + g * 4) = make_float4(y0, y1, y2, y3);
        }
        __syncthreads();

        // Phase B1: frames 0..252
        if (tid < 253) {
            const int f = tid;
            const float4 A0 = *reinterpret_cast<const float4*>(sm + I_OFF_WAV + f * 4);
            const float4 A1 = *reinterpret_cast<const float4*>(sm + I_OFF_WAV + (f + 1) * 4);
            const float4 A2 = *reinterpret_cast<const float4*>(sm + I_OFF_WAV + (f + 2) * 4);
            const float4 A3 = *reinterpret_cast<const float4*>(sm + I_OFF_WAV + (f + 3) * 4);
            const float4 MS = *reinterpret_cast<const float4*>(sm + I_OFF_S + (f + 3) * 4);
            const float4 MD = *reinterpret_cast<const float4*>(sm + I_OFF_D + (f + 3) * 4);
            float4 R0, R1, R2, R3;
            processFrame(A0, A1, A2, A3, MS, MD, sm[I_OFF_M4 + f + 3], R0, R1, R2, R3);
            *reinterpret_cast<float4*>(sm + I_OFF_P0 + f * 4) = R0;
            *reinterpret_cast<float4*>(sm + I_OFF_P1 + f * 4) = R1;
            *reinterpret_cast<float4*>(sm + I_OFF_P2 + f * 4) = R2;
            *reinterpret_cast<float4*>(sm + I_OFF_P3 + f * 4) = R3;
        }
        __syncthreads();

        // Phase B2: overlap-add, groups 0..249
        if (tid < 250) {
            const int g = tid;
            const float4 q3 = *reinterpret_cast<const float4*>(sm + I_OFF_P3 + g * 4);
            const float4 q2 = *reinterpret_cast<const float4*>(sm + I_OFF_P2 + (g + 1) * 4);
            const float4 q1 = *reinterpret_cast<const float4*>(sm + I_OFF_P1 + (g + 2) * 4);
            const float4 q0 = *reinterpret_cast<const float4*>(sm + I_OFF_P0 + (g + 3) * 4);
            float* outb = out + (size_t)b * LOUT + s0;
            *reinterpret_cast<float4*>(outb + 4 * g) = make_float4(
                ((q0.x + q1.x) + (q2.x + q3.x)) * EINVc(0),
                ((q0.y + q1.y) + (q2.y + q3.y)) * EINVc(1),
                ((q0.z + q1.z) + (q2.z + q3.z)) * EINVc(2),
                ((q0.w + q1.w) + (q2.w + q3.w)) * EINVc(3));
        }
    } else {
        // ================= EDGE body (tiles 0 and NT-1) =====================
        const int s0   = bx * OT;
        const int nout = min(OT, LOUT - s0);
        const int F0   = s0 >> 2;
        const int TLO  = max(0, F0 - 1);
        const int THI  = min(TFR - 1, (s0 + nout + 7) >> 2);
        const int NFR  = THI - TLO + 1;
        const int tM0  = TLO - 3;
        const int ROWS = NFR + 7;

        #pragma unroll
        for (int pass = 0; pass < 2; pass++) {
            const int tt = tid + pass * NTHR;
            if (tt < ROWS) {
                const int tg = tM0 + tt;
                float4 S, D; float m4;
                if (tg >= 0 && tg < TFR) {
                    const float* gp = magb + tg;
                    const float a0 = __ldg(gp);            const float a8 = __ldg(gp + 8 * TFR);
                    const float a1 = __ldg(gp + 1 * TFR);  const float a7 = __ldg(gp + 7 * TFR);
                    const float a2 = __ldg(gp + 2 * TFR);  const float a6 = __ldg(gp + 6 * TFR);
                    const float a3 = __ldg(gp + 3 * TFR);  const float a5 = __ldg(gp + 5 * TFR);
                    m4 = __ldg(gp + 4 * TFR);
                    S = make_float4(a0 + a8, a1 + a7, a2 + a6, a3 + a5);
                    D = make_float4(a0 - a8, a1 - a7, a2 - a6, a3 - a5);
                } else {
                    S = make_float4(0.f, 0.f, 0.f, 0.f);
                    D = S; m4 = 0.f;
                }
                *reinterpret_cast<float4*>(sm + I_OFF_S + tt * 4) = S;
                *reinterpret_cast<float4*>(sm + I_OFF_D + tt * 4) = D;
                sm[I_OFF_M4 + tt] = m4;
            }
        }
        __syncthreads();

        // Phase A
        const int ngA = NFR + 3;
        if (tid < ngA) {
            const int g     = tid;
            const int jbase = 4 * TLO - 8 + 4 * g;
            const int X     = TLO + g;
            if (jbase >= 0 && jbase + 3 < LOUT && X >= 3 && X <= TFR - 1) {
                float y0 = 0.f, y1 = 0.f, y2 = 0.f, y3 = 0.f;
                {   const float4 u0 = *reinterpret_cast<const float4*>(sm + I_OFF_S + g * 4);
                    const float4 u1 = *reinterpret_cast<const float4*>(sm + I_OFF_D + g * 4);
                    accA<3>(u0, u1, sm[I_OFF_M4 + g], y0, y1, y2, y3); }
                {   const float4 u0 = *reinterpret_cast<const float4*>(sm + I_OFF_S + (g + 1) * 4);
                    const float4 u1 = *reinterpret_cast<const float4*>(sm + I_OFF_D + (g + 1) * 4);
                    accA<2>(u0, u1, sm[I_OFF_M4 + g + 1], y0, y1, y2, y3); }
                {   const float4 u0 = *reinterpret_cast<const float4*>(sm + I_OFF_S + (g + 2) * 4);
                    const float4 u1 = *reinterpret_cast<const float4*>(sm + I_OFF_D + (g + 2) * 4);
                    accA<1>(u0, u1, sm[I_OFF_M4 + g + 2], y0, y1, y2, y3); }
                {   const float4 u0 = *reinterpret_cast<const float4*>(sm + I_OFF_S + (g + 3) * 4);
                    const float4 u1 = *reinterpret_cast<const float4*>(sm + I_OFF_D + (g + 3) * 4);
                    accA<0>(u0, u1, sm[I_OFF_M4 + g + 3], y0, y1, y2, y3); }
                *reinterpret_cast<float4*>(sm + I_OFF_WAV + g * 4) = make_float4(y0, y1, y2, y3);
            } else {
                float* wp = sm + I_OFF_WAV + g * 4;
                for (int r = 0; r < 4; r++) {
                    const int jg = jbase + r;
                    const int jr = (jg < 0) ? -jg : ((jg >= LOUT) ? 2 * LOUT - 2 - jg : jg);
                    const int p  = jr + 8;
                    const int Xp = p >> 2;
                    const int rr = p & 3;
                    float acc = 0.f, env = 0.f;
                    for (int jj = 0; jj < 4; jj++) {
                        const int tt = Xp - jj;
                        if (tt < 0 || tt >= TFR) continue;
                        const int n = rr + 4 * jj;
                        const float w = W16T[n];
                        const int row = tt - tM0;
                        const float* sp = sm + I_OFF_S + row * 4;
                        const float* dp = sm + I_OFF_D + row * 4;
                        float ssum;
                        if (n & 1) {
                            ssum = dp[0]
                                 + 2.f * (dp[1] * C8T[n & 15] + dp[2] * C8T[(2 * n) & 15] + dp[3] * C8T[(3 * n) & 15]);
                        } else {
                            ssum = sp[0]
                                 + 2.f * (sp[1] * C8T[n & 15] + sp[2] * C8T[(2 * n) & 15] + sp[3] * C8T[(3 * n) & 15]
                                        + sm[I_OFF_M4 + row] * C8T[(4 * n) & 15]);
                        }
                        acc = fmaf(ssum, 0.0625f * w, acc);
                        env = fmaf(w, w, env);
                    }
                    wp[r] = acc / env;
                }
            }
        }
        __syncthreads();

        // Phase B1
        if (tid < NFR) {
            const int f = tid;
            const float4 A0 = *reinterpret_cast<const float4*>(sm + I_OFF_WAV + f * 4);
            const float4 A1 = *reinterpret_cast<const float4*>(sm + I_OFF_WAV + (f + 1) * 4);
            const float4 A2 = *reinterpret_cast<const float4*>(sm + I_OFF_WAV + (f + 2) * 4);
            const float4 A3 = *reinterpret_cast<const float4*>(sm + I_OFF_WAV + (f + 3) * 4);
            const float4 MS = *reinterpret_cast<const float4*>(sm + I_OFF_S + (f + 3) * 4);
            const float4 MD = *reinterpret_cast<const float4*>(sm + I_OFF_D + (f + 3) * 4);
            float4 R0, R1, R2, R3;
            processFrame(A0, A1, A2, A3, MS, MD, sm[I_OFF_M4 + f + 3], R0, R1, R2, R3);
            *reinterpret_cast<float4*>(sm + I_OFF_P0 + f * 4) = R0;
            *reinterpret_cast<float4*>(sm + I_OFF_P1 + f * 4) = R1;
            *reinterpret_cast<float4*>(sm + I_OFF_P2 + f * 4) = R2;
            *reinterpret_cast<float4*>(sm + I_OFF_P3 + f * 4) = R3;
        }
        __syncthreads();

        // Phase B2
        const int ngO = (nout + 3) >> 2;
        float* outb = out + (size_t)b * LOUT + s0;
        if (tid < ngO) {
            const int g = tid;
            const int X = F0 + g + 2;
            const bool wholeGroup = (4 * g + 3 < nout);
            if (wholeGroup && X - 3 >= TLO && X <= THI) {
                const int Rb = X - TLO - 3;
                const float4 q3 = *reinterpret_cast<const float4*>(sm + I_OFF_P3 + Rb * 4);
                const float4 q2 = *reinterpret_cast<const float4*>(sm + I_OFF_P2 + (Rb + 1) * 4);
                const float4 q1 = *reinterpret_cast<const float4*>(sm + I_OFF_P1 + (Rb + 2) * 4);
                const float4 q0 = *reinterpret_cast<const float4*>(sm + I_OFF_P0 + (Rb + 3) * 4);
                *reinterpret_cast<float4*>(outb + 4 * g) = make_float4(
                    ((q0.x + q1.x) + (q2.x + q3.x)) * EINVc(0),
                    ((q0.y + q1.y) + (q2.y + q3.y)) * EINVc(1),
                    ((q0.z + q1.z) + (q2.z + q3.z)) * EINVc(2),
                    ((q0.w + q1.w) + (q2.w + q3.w)) * EINVc(3));
            } else {
                for (int r = 0; r < 4; r++) {
                    const int so = 4 * g + r;
                    if (so >= nout) break;
                    const int s  = s0 + so;
                    const int p  = s + 8;
                    const int Xp = p >> 2;
                    const int rr = p & 3;
                    float acc = 0.f, env = 0.f;
                    for (int jj = 0; jj < 4; jj++) {
                        const int tt = Xp - jj;
                        if (tt < TLO || tt > THI) continue;
                        const int n = rr + 4 * jj;
                        const float w = W16T[n];
                        acc += sm[I_OFF_P0 + (n >> 2) * PPLANE + (tt - TLO) * 4 + (n & 3)];
                        env = fmaf(w, w, env);
                    }
                    outb[so] = acc / env;
                }
            }
        }
    }
}

// ---------------------------------------------------------------------------
extern "C" void kernel_launch(void* const* d_in, const int* in_sizes, int n_in,
                              void* d_out, int out_size)
{
    (void)in_sizes; (void)n_in; (void)out_size;
    const float* mag = (const float*)d_in[0];
    float* out = (float*)d_out;
    // Maximize shared carveout; 29.6 KB/CTA -> 7 CTAs/SM.
    cudaFuncSetAttribute(glim_kernel, cudaFuncAttributePreferredSharedMemoryCarveout, 100);
    dim3 grid(NT, BATCH);
    glim_kernel<<<grid, NTHR>>>(mag, out);
}

// round 12
// speedup vs baseline: 1.2729x; 1.1252x over previous
#include <cuda_runtime.h>

// ---------------------------------------------------------------------------
// Problem constants
// ---------------------------------------------------------------------------
constexpr int TFR   = 65536;
constexpr int KB9   = 9;
constexpr int BATCH = 32;
constexpr int LOUT  = (TFR - 1) * 4;            // 262140

constexpr int OT   = 1000;                      // output samples per tile
constexpr int NT   = (LOUT + OT - 1) / OT;      // 263 tiles
constexpr int NTHR = 256;

// Plane layout (word offsets); every access is a stride-4 .128 -> conflict-free.
constexpr int I_OFF_S   = 0;                     // S plane: 260 x 4
constexpr int I_OFF_D   = 1040;                  // D plane: 260 x 4
constexpr int I_OFF_M4  = 2080;                  // m4 plane: 260
constexpr int I_OFF_WAV = 2340;                  // wav plane: 256 x 4
constexpr int I_OFF_P0  = 3364;                  // P chunk planes: 253 x 4 each
constexpr int I_OFF_P1  = 4376;
constexpr int I_OFF_P2  = 5388;
constexpr int I_OFF_P3  = 6400;                  // stored only by EDGE body
constexpr int I_SMW     = 7412;                  // 29648 bytes
constexpr int PPLANE    = 1012;                  // words per P plane

// ---------------------------------------------------------------------------
// Compile-time twiddles (all angles multiples of pi/8)
// ---------------------------------------------------------------------------
#define HD __host__ __device__ __forceinline__

HD constexpr float cos8c(int m) {
    m &= 15;
    const int mm = m & 7;
    const float v =
        (mm == 0) ?  1.0f :
        (mm == 1) ?  0.92387953251128674f :
        (mm == 2) ?  0.70710678118654752f :
        (mm == 3) ?  0.38268343236508977f :
        (mm == 4) ?  0.0f :
        (mm == 5) ? -0.38268343236508977f :
        (mm == 6) ? -0.70710678118654752f :
                    -0.92387953251128674f;
    return (m & 8) ? -v : v;
}
HD constexpr float sin8c(int m) { return cos8c(m + 12); }
HD constexpr float wwinc(int n) { return 0.5f - 0.5f * cos8c(n); }   // hann(16)
HD constexpr float CSc(int k, int n) { return ((k == 0) ? 1.0f : 2.0f) * 0.0625f * cos8c(k * n) * wwinc(n); }
HD constexpr float envsum(int r) {
    return wwinc(r)      * wwinc(r)      + wwinc(r + 4)  * wwinc(r + 4)
         + wwinc(r + 8)  * wwinc(r + 8)  + wwinc(r + 12) * wwinc(r + 12);
}
HD constexpr float EINVc(int r) { return 1.0f / envsum(r); }
HD constexpr float CSF(int k, int n) { return CSc(k, n) * EINVc(n & 3); }
HD constexpr float W8c(int n) { return wwinc(n) * 0.125f; }

// Runtime tables (edge fallbacks only)
__constant__ float C8T[16] = { cos8c(0), cos8c(1), cos8c(2), cos8c(3), cos8c(4), cos8c(5), cos8c(6), cos8c(7),
                               cos8c(8), cos8c(9), cos8c(10), cos8c(11), cos8c(12), cos8c(13), cos8c(14), cos8c(15) };
__constant__ float W16T[16] = { wwinc(0), wwinc(1), wwinc(2), wwinc(3), wwinc(4), wwinc(5), wwinc(6), wwinc(7),
                                wwinc(8), wwinc(9), wwinc(10), wwinc(11), wwinc(12), wwinc(13), wwinc(14), wwinc(15) };

// ---------------------------------------------------------------------------
// Phase-A accumulator (env folded in; fully constant-folded)
// ---------------------------------------------------------------------------
template<int JJ>
__device__ __forceinline__ void accA(const float4 u0, const float4 u1, const float m4,
                                     float& y0, float& y1, float& y2, float& y3)
{
    { constexpr int n = 4 * JJ + 0;
      if (CSF(0,n) != 0.f) y0 = fmaf(u0.x, CSF(0,n), y0);
      if (CSF(1,n) != 0.f) y0 = fmaf(u0.y, CSF(1,n), y0);
      if (CSF(2,n) != 0.f) y0 = fmaf(u0.z, CSF(2,n), y0);
      if (CSF(3,n) != 0.f) y0 = fmaf(u0.w, CSF(3,n), y0);
      if (CSF(4,n) != 0.f) y0 = fmaf(m4,   CSF(4,n), y0); }
    { constexpr int n = 4 * JJ + 1;
      if (CSF(0,n) != 0.f) y1 = fmaf(u1.x, CSF(0,n), y1);
      if (CSF(1,n) != 0.f) y1 = fmaf(u1.y, CSF(1,n), y1);
      if (CSF(2,n) != 0.f) y1 = fmaf(u1.z, CSF(2,n), y1);
      if (CSF(3,n) != 0.f) y1 = fmaf(u1.w, CSF(3,n), y1); }
    { constexpr int n = 4 * JJ + 2;
      if (CSF(0,n) != 0.f) y2 = fmaf(u0.x, CSF(0,n), y2);
      if (CSF(1,n) != 0.f) y2 = fmaf(u0.y, CSF(1,n), y2);
      if (CSF(2,n) != 0.f) y2 = fmaf(u0.z, CSF(2,n), y2);
      if (CSF(3,n) != 0.f) y2 = fmaf(u0.w, CSF(3,n), y2);
      if (CSF(4,n) != 0.f) y2 = fmaf(m4,   CSF(4,n), y2); }
    { constexpr int n = 4 * JJ + 3;
      if (CSF(0,n) != 0.f) y3 = fmaf(u1.x, CSF(0,n), y3);
      if (CSF(1,n) != 0.f) y3 = fmaf(u1.y, CSF(1,n), y3);
      if (CSF(2,n) != 0.f) y3 = fmaf(u1.z, CSF(2,n), y3);
      if (CSF(3,n) != 0.f) y3 = fmaf(u1.w, CSF(3,n), y3); }
}

// ---------------------------------------------------------------------------
// B1 frame processing, FFT-folded; result in registers.
// ---------------------------------------------------------------------------
__device__ __forceinline__ void processFrame(const float4 A0, const float4 A1,
                                             const float4 A2, const float4 A3,
                                             const float4 MS, const float4 MD, const float m4v,
                                             float4& R0, float4& R1, float4& R2, float4& R3)
{
    constexpr float c1 = 0.92387953251128674f;   // cos(pi/8)
    constexpr float c2 = 0.70710678118654752f;   // cos(pi/4)
    constexpr float c3 = 0.38268343236508977f;   // cos(3pi/8)

    const float x8 = A2.x;
    const float e1 = wwinc(1) * (A0.y + A3.w), o1 = wwinc(1) * (A0.y - A3.w);
    const float e2 = wwinc(2) * (A0.z + A3.z), o2 = wwinc(2) * (A0.z - A3.z);
    const float e3 = wwinc(3) * (A0.w + A3.y), o3 = wwinc(3) * (A0.w - A3.y);
    const float e4 = wwinc(4) * (A1.x + A3.x), o4 = wwinc(4) * (A1.x - A3.x);
    const float e5 = wwinc(5) * (A1.y + A2.w), o5 = wwinc(5) * (A1.y - A2.w);
    const float e6 = wwinc(6) * (A1.z + A2.z), o6 = wwinc(6) * (A1.z - A2.z);
    const float e7 = wwinc(7) * (A1.w + A2.y), o7 = wwinc(7) * (A1.w - A2.y);

    const float es1 = e1 + e7, es2 = e2 + e6, es3 = e3 + e5;
    const float ed1 = e1 - e7, ed2 = e2 - e6, ed3 = e3 - e5;
    const float os1 = o1 + o7, os2 = o2 + o6, os3 = o3 + o5;
    const float od1 = o1 - o7, od2 = o2 - o6, od3 = o3 - o5;

    float re[9], im[9];
    {   const float t1 = c2 * (es1 - es3);
        const float t2 = x8 - e4, t3 = x8 + e4;
        const float q  = es1 + es3;
        const float Aa = t3 + es2;
        re[0] = Aa + q;  re[8] = Aa - q;
        re[2] = t2 + t1; re[6] = t2 - t1;
        re[4] = t3 - es2; }
    {   const float m  = ed2 * c2;
        const float v  = m - x8, w = -m - x8;
        const float u  = fmaf(ed1, c1,  ed3 * c3);
        const float u2 = fmaf(ed1, c3, -(ed3 * c1));
        re[1] = v + u;  re[7] = v - u;
        re[3] = w + u2; re[5] = w - u2; }
    {   const float a  = fmaf(os1, c3,  os3 * c1);
        const float b  = fmaf(os2, c2,  o4);
        const float a2 = fmaf(os1, c1, -(os3 * c3));
        const float b2 = fmaf(os2, c2, -o4);
        im[1] = -(a + b);   im[3] = -(a2 + b2);
        im[5] = b2 - a2;    im[7] = b - a; }
    {   const float t4 = c2 * (od1 + od3);
        im[2] = -(t4 + od2); im[6] = od2 - t4; im[4] = od3 - od1; }

    float mv[9];
    mv[0] = 0.5f * (MS.x + MD.x);  mv[8] = 0.5f * (MS.x - MD.x);
    mv[1] = 0.5f * (MS.y + MD.y);  mv[7] = 0.5f * (MS.y - MD.y);
    mv[2] = 0.5f * (MS.z + MD.z);  mv[6] = 0.5f * (MS.z - MD.z);
    mv[3] = 0.5f * (MS.w + MD.w);  mv[5] = 0.5f * (MS.w - MD.w);
    mv[4] = m4v;

    float ca[9], sa[9];
    ca[0] = copysignf(mv[0], re[0]);
    ca[8] = copysignf(mv[8], re[8]);
    #pragma unroll
    for (int k = 1; k < 8; k++) {
        const float n2 = fmaf(re[k], re[k], im[k] * im[k]);
        if (n2 > 0.f) {
            const float u = mv[k] * rsqrtf(n2);
            ca[k] = re[k] * u;
            sa[k] = im[k] * u;
        } else {
            ca[k] = mv[k];
            sa[k] = 0.f;
        }
    }

    const float Ai1 = ca[1] + ca[7], Ai2 = ca[2] + ca[6], Ai3 = ca[3] + ca[5];
    const float Ci1 = ca[1] - ca[7], Ci2 = ca[2] - ca[6], Ci3 = ca[3] - ca[5];
    const float Si1 = sa[1] + sa[7], Si2 = sa[2] + sa[6], Si3 = sa[3] + sa[5];
    const float Di1 = sa[1] - sa[7], Di2 = sa[2] - sa[6], Di3 = sa[3] - sa[5];
    const float z2  = 0.5f * (ca[0] + ca[8]);
    const float z2p = 0.5f * (ca[0] - ca[8]);
    const float ca4 = ca[4], sa4 = sa[4];

    const float h1 = c2 * (Ai1 - Ai3);
    const float h2 = c2 * (Di1 + Di3);
    const float za = z2 - ca4, zb = z2 + ca4;
    const float E2 = za + h1, E6 = za - h1, E4 = zb - Ai2;
    const float O2 = h2 + Di2, O6 = h2 - Di2, O4 = Di1 - Di3;
    const float s8  = (zb + Ai2) - (Ai1 + Ai3);
    const float s2  = E2 - O2, s14 = E2 + O2;
    const float s4  = E4 - O4, s12 = E4 + O4;
    const float s6  = E6 - O6, s10 = E6 + O6;

    const float mC  = Ci2 * c2;
    const float uE  = fmaf(Ci1, c1,  Ci3 * c3);
    const float u2E = fmaf(Ci1, c3, -(Ci3 * c1));
    const float ta  = z2p + mC, tb = z2p - mC;
    const float E1 = ta + uE, E7 = ta - uE, E3 = tb + u2E, E5 = tb - u2E;
    const float nS  = Si2 * c2;
    const float vO  = fmaf(Si1, c3,  Si3 * c1);
    const float v2O = fmaf(Si1, c1, -(Si3 * c3));
    const float wo = nS + sa4, w2o = nS - sa4;
    const float O1 = vO + wo, O7 = vO - wo, O3 = v2O + w2o, O5 = v2O - w2o;
    const float s1  = E1 - O1, s15 = E1 + O1;
    const float s3  = E3 - O3, s13 = E3 + O3;
    const float s5  = E5 - O5, s11 = E5 + O5;
    const float s7  = E7 - O7, s9  = E7 + O7;

    R0 = make_float4(0.f,         W8c(1)*s1,   W8c(2)*s2,   W8c(3)*s3);
    R1 = make_float4(W8c(4)*s4,   W8c(5)*s5,   W8c(6)*s6,   W8c(7)*s7);
    R2 = make_float4(W8c(8)*s8,   W8c(9)*s9,   W8c(10)*s10, W8c(11)*s11);
    R3 = make_float4(W8c(12)*s12, W8c(13)*s13, W8c(14)*s14, W8c(15)*s15);
}

// ---------------------------------------------------------------------------
// Fused kernel. Interior CTAs: constant geometry + register-carried
// producer->consumer values (own S/D/m4 row, own wav group, own P3 chunk).
// Edge CTAs (2 per batch row): bounds-checked body on the same smem planes.
// Branch is CTA-uniform, so divergent __syncthreads are safe.
// ---------------------------------------------------------------------------
__global__ void __launch_bounds__(NTHR, 7)
glim_kernel(const float* __restrict__ mag, float* __restrict__ out)
{
    __shared__ __align__(16) float sm[I_SMW];

    const int tid = threadIdx.x;
    const int bx  = blockIdx.x;
    const int b   = blockIdx.y;
    const float* magb = mag + (size_t)b * (KB9 * TFR);

    if (bx > 0 && bx < NT - 1) {
        // ================= INTERIOR body =================
        const int s0  = bx * OT;
        const int F0  = s0 >> 2;
        const int tM0 = F0 - 4;
        // constants: NFR = 253, ngA = 256, ngO = 250, ROWS = 260

        // ---- stage; keep own (pass-0) row in registers ----
        float4 rS, rD; float rM4;
        {
            const float* gp = magb + (tM0 + tid);
            const float a0 = __ldg(gp);            const float a8 = __ldg(gp + 8 * TFR);
            const float a1 = __ldg(gp + 1 * TFR);  const float a7 = __ldg(gp + 7 * TFR);
            const float a2 = __ldg(gp + 2 * TFR);  const float a6 = __ldg(gp + 6 * TFR);
            const float a3 = __ldg(gp + 3 * TFR);  const float a5 = __ldg(gp + 5 * TFR);
            rS  = make_float4(a0 + a8, a1 + a7, a2 + a6, a3 + a5);
            rD  = make_float4(a0 - a8, a1 - a7, a2 - a6, a3 - a5);
            rM4 = __ldg(gp + 4 * TFR);
            *reinterpret_cast<float4*>(sm + I_OFF_S + tid * 4) = rS;
            *reinterpret_cast<float4*>(sm + I_OFF_D + tid * 4) = rD;
            sm[I_OFF_M4 + tid] = rM4;
        }
        {
            const int tt = tid + NTHR;
            if (tt < 260) {
                const float* gp = magb + (tM0 + tt);
                const float a0 = __ldg(gp);            const float a8 = __ldg(gp + 8 * TFR);
                const float a1 = __ldg(gp + 1 * TFR);  const float a7 = __ldg(gp + 7 * TFR);
                const float a2 = __ldg(gp + 2 * TFR);  const float a6 = __ldg(gp + 6 * TFR);
                const float a3 = __ldg(gp + 3 * TFR);  const float a5 = __ldg(gp + 5 * TFR);
                *reinterpret_cast<float4*>(sm + I_OFF_S + tt * 4) =
                    make_float4(a0 + a8, a1 + a7, a2 + a6, a3 + a5);
                *reinterpret_cast<float4*>(sm + I_OFF_D + tt * 4) =
                    make_float4(a0 - a8, a1 - a7, a2 - a6, a3 - a5);
                sm[I_OFF_M4 + tt] = __ldg(gp + 4 * TFR);
            }
        }
        __syncthreads();

        // ---- Phase A: own row from regs, rows g+1..g+3 from smem ----
        float ay0 = 0.f, ay1 = 0.f, ay2 = 0.f, ay3 = 0.f;
        {
            const int g = tid;
            accA<3>(rS, rD, rM4, ay0, ay1, ay2, ay3);
            {   const float4 u0 = *reinterpret_cast<const float4*>(sm + I_OFF_S + (g + 1) * 4);
                const float4 u1 = *reinterpret_cast<const float4*>(sm + I_OFF_D + (g + 1) * 4);
                accA<2>(u0, u1, sm[I_OFF_M4 + g + 1], ay0, ay1, ay2, ay3); }
            {   const float4 u0 = *reinterpret_cast<const float4*>(sm + I_OFF_S + (g + 2) * 4);
                const float4 u1 = *reinterpret_cast<const float4*>(sm + I_OFF_D + (g + 2) * 4);
                accA<1>(u0, u1, sm[I_OFF_M4 + g + 2], ay0, ay1, ay2, ay3); }
            {   const float4 u0 = *reinterpret_cast<const float4*>(sm + I_OFF_S + (g + 3) * 4);
                const float4 u1 = *reinterpret_cast<const float4*>(sm + I_OFF_D + (g + 3) * 4);
                accA<0>(u0, u1, sm[I_OFF_M4 + g + 3], ay0, ay1, ay2, ay3); }
            *reinterpret_cast<float4*>(sm + I_OFF_WAV + g * 4) = make_float4(ay0, ay1, ay2, ay3);
        }
        __syncthreads();

        // ---- Phase B1: own wav group from regs; keep own R3 for B2 ----
        float4 R3own;
        if (tid < 253) {
            const int f = tid;
            const float4 A0 = make_float4(ay0, ay1, ay2, ay3);
            const float4 A1 = *reinterpret_cast<const float4*>(sm + I_OFF_WAV + (f + 1) * 4);
            const float4 A2 = *reinterpret_cast<const float4*>(sm + I_OFF_WAV + (f + 2) * 4);
            const float4 A3 = *reinterpret_cast<const float4*>(sm + I_OFF_WAV + (f + 3) * 4);
            const float4 MS = *reinterpret_cast<const float4*>(sm + I_OFF_S + (f + 3) * 4);
            const float4 MD = *reinterpret_cast<const float4*>(sm + I_OFF_D + (f + 3) * 4);
            float4 R0, R1, R2, R3;
            processFrame(A0, A1, A2, A3, MS, MD, sm[I_OFF_M4 + f + 3], R0, R1, R2, R3);
            *reinterpret_cast<float4*>(sm + I_OFF_P0 + f * 4) = R0;
            *reinterpret_cast<float4*>(sm + I_OFF_P1 + f * 4) = R1;
            *reinterpret_cast<float4*>(sm + I_OFF_P2 + f * 4) = R2;
            R3own = R3;                                      // P3 plane never stored
        }
        __syncthreads();

        // ---- Phase B2: overlap-add (q3 from registers) ----
        if (tid < 250) {
            const int g = tid;
            const float4 q2 = *reinterpret_cast<const float4*>(sm + I_OFF_P2 + (g + 1) * 4);
            const float4 q1 = *reinterpret_cast<const float4*>(sm + I_OFF_P1 + (g + 2) * 4);
            const float4 q0 = *reinterpret_cast<const float4*>(sm + I_OFF_P0 + (g + 3) * 4);
            float* outb = out + (size_t)b * LOUT + s0;
            *reinterpret_cast<float4*>(outb + 4 * g) = make_float4(
                ((q0.x + q1.x) + (q2.x + R3own.x)) * EINVc(0),
                ((q0.y + q1.y) + (q2.y + R3own.y)) * EINVc(1),
                ((q0.z + q1.z) + (q2.z + R3own.z)) * EINVc(2),
                ((q0.w + q1.w) + (q2.w + R3own.w)) * EINVc(3));
        }
    } else {
        // ================= EDGE body (tiles 0 and NT-1) =================
        const int s0   = bx * OT;
        const int nout = min(OT, LOUT - s0);
        const int F0   = s0 >> 2;
        const int TLO  = max(0, F0 - 1);
        const int THI  = min(TFR - 1, (s0 + nout + 7) >> 2);
        const int NFR  = THI - TLO + 1;
        const int tM0  = TLO - 3;
        const int ROWS = NFR + 7;

        #pragma unroll
        for (int pass = 0; pass < 2; pass++) {
            const int tt = tid + pass * NTHR;
            if (tt < ROWS) {
                const int tg = tM0 + tt;
                float4 S, D; float m4;
                if (tg >= 0 && tg < TFR) {
                    const float* gp = magb + tg;
                    const float a0 = __ldg(gp);            const float a8 = __ldg(gp + 8 * TFR);
                    const float a1 = __ldg(gp + 1 * TFR);  const float a7 = __ldg(gp + 7 * TFR);
                    const float a2 = __ldg(gp + 2 * TFR);  const float a6 = __ldg(gp + 6 * TFR);
                    const float a3 = __ldg(gp + 3 * TFR);  const float a5 = __ldg(gp + 5 * TFR);
                    m4 = __ldg(gp + 4 * TFR);
                    S = make_float4(a0 + a8, a1 + a7, a2 + a6, a3 + a5);
                    D = make_float4(a0 - a8, a1 - a7, a2 - a6, a3 - a5);
                } else {
                    S = make_float4(0.f, 0.f, 0.f, 0.f);
                    D = S; m4 = 0.f;
                }
                *reinterpret_cast<float4*>(sm + I_OFF_S + tt * 4) = S;
                *reinterpret_cast<float4*>(sm + I_OFF_D + tt * 4) = D;
                sm[I_OFF_M4 + tt] = m4;
            }
        }
        __syncthreads();

        // Phase A
        const int ngA = NFR + 3;
        if (tid < ngA) {
            const int g     = tid;
            const int jbase = 4 * TLO - 8 + 4 * g;
            const int X     = TLO + g;
            if (jbase >= 0 && jbase + 3 < LOUT && X >= 3 && X <= TFR - 1) {
                float y0 = 0.f, y1 = 0.f, y2 = 0.f, y3 = 0.f;
                {   const float4 u0 = *reinterpret_cast<const float4*>(sm + I_OFF_S + g * 4);
                    const float4 u1 = *reinterpret_cast<const float4*>(sm + I_OFF_D + g * 4);
                    accA<3>(u0, u1, sm[I_OFF_M4 + g], y0, y1, y2, y3); }
                {   const float4 u0 = *reinterpret_cast<const float4*>(sm + I_OFF_S + (g + 1) * 4);
                    const float4 u1 = *reinterpret_cast<const float4*>(sm + I_OFF_D + (g + 1) * 4);
                    accA<2>(u0, u1, sm[I_OFF_M4 + g + 1], y0, y1, y2, y3); }
                {   const float4 u0 = *reinterpret_cast<const float4*>(sm + I_OFF_S + (g + 2) * 4);
                    const float4 u1 = *reinterpret_cast<const float4*>(sm + I_OFF_D + (g + 2) * 4);
                    accA<1>(u0, u1, sm[I_OFF_M4 + g + 2], y0, y1, y2, y3); }
                {   const float4 u0 = *reinterpret_cast<const float4*>(sm + I_OFF_S + (g + 3) * 4);
                    const float4 u1 = *reinterpret_cast<const float4*>(sm + I_OFF_D + (g + 3) * 4);
                    accA<0>(u0, u1, sm[I_OFF_M4 + g + 3], y0, y1, y2, y3); }
                *reinterpret_cast<float4*>(sm + I_OFF_WAV + g * 4) = make_float4(y0, y1, y2, y3);
            } else {
                float* wp = sm + I_OFF_WAV + g * 4;
                for (int r = 0; r < 4; r++) {
                    const int jg = jbase + r;
                    const int jr = (jg < 0) ? -jg : ((jg >= LOUT) ? 2 * LOUT - 2 - jg : jg);
                    const int p  = jr + 8;
                    const int Xp = p >> 2;
                    const int rr = p & 3;
                    float acc = 0.f, env = 0.f;
                    for (int jj = 0; jj < 4; jj++) {
                        const int tt = Xp - jj;
                        if (tt < 0 || tt >= TFR) continue;
                        const int n = rr + 4 * jj;
                        const float w = W16T[n];
                        const int row = tt - tM0;
                        const float* sp = sm + I_OFF_S + row * 4;
                        const float* dp = sm + I_OFF_D + row * 4;
                        float ssum;
                        if (n & 1) {
                            ssum = dp[0]
                                 + 2.f * (dp[1] * C8T[n & 15] + dp[2] * C8T[(2 * n) & 15] + dp[3] * C8T[(3 * n) & 15]);
                        } else {
                            ssum = sp[0]
                                 + 2.f * (sp[1] * C8T[n & 15] + sp[2] * C8T[(2 * n) & 15] + sp[3] * C8T[(3 * n) & 15]
                                        + sm[I_OFF_M4 + row] * C8T[(4 * n) & 15]);
                        }
                        acc = fmaf(ssum, 0.0625f * w, acc);
                        env = fmaf(w, w, env);
                    }
                    wp[r] = acc / env;
                }
            }
        }
        __syncthreads();

        // Phase B1 (stores all four P planes, incl. P3, for the fallbacks)
        if (tid < NFR) {
            const int f = tid;
            const float4 A0 = *reinterpret_cast<const float4*>(sm + I_OFF_WAV + f * 4);
            const float4 A1 = *reinterpret_cast<const float4*>(sm + I_OFF_WAV + (f + 1) * 4);
            const float4 A2 = *reinterpret_cast<const float4*>(sm + I_OFF_WAV + (f + 2) * 4);
            const float4 A3 = *reinterpret_cast<const float4*>(sm + I_OFF_WAV + (f + 3) * 4);
            const float4 MS = *reinterpret_cast<const float4*>(sm + I_OFF_S + (f + 3) * 4);
            const float4 MD = *reinterpret_cast<const float4*>(sm + I_OFF_D + (f + 3) * 4);
            float4 R0, R1, R2, R3;
            processFrame(A0, A1, A2, A3, MS, MD, sm[I_OFF_M4 + f + 3], R0, R1, R2, R3);
            *reinterpret_cast<float4*>(sm + I_OFF_P0 + f * 4) = R0;
            *reinterpret_cast<float4*>(sm + I_OFF_P1 + f * 4) = R1;
            *reinterpret_cast<float4*>(sm + I_OFF_P2 + f * 4) = R2;
            *reinterpret_cast<float4*>(sm + I_OFF_P3 + f * 4) = R3;
        }
        __syncthreads();

        // Phase B2
        const int ngO = (nout + 3) >> 2;
        float* outb = out + (size_t)b * LOUT + s0;
        if (tid < ngO) {
            const int g = tid;
            const int X = F0 + g + 2;
            const bool wholeGroup = (4 * g + 3 < nout);
            if (wholeGroup && X - 3 >= TLO && X <= THI) {
                const int Rb = X - TLO - 3;
                const float4 q3 = *reinterpret_cast<const float4*>(sm + I_OFF_P3 + Rb * 4);
                const float4 q2 = *reinterpret_cast<const float4*>(sm + I_OFF_P2 + (Rb + 1) * 4);
                const float4 q1 = *reinterpret_cast<const float4*>(sm + I_OFF_P1 + (Rb + 2) * 4);
                const float4 q0 = *reinterpret_cast<const float4*>(sm + I_OFF_P0 + (Rb + 3) * 4);
                *reinterpret_cast<float4*>(outb + 4 * g) = make_float4(
                    ((q0.x + q1.x) + (q2.x + q3.x)) * EINVc(0),
                    ((q0.y + q1.y) + (q2.y + q3.y)) * EINVc(1),
                    ((q0.z + q1.z) + (q2.z + q3.z)) * EINVc(2),
                    ((q0.w + q1.w) + (q2.w + q3.w)) * EINVc(3));
            } else {
                for (int r = 0; r < 4; r++) {
                    const int so = 4 * g + r;
                    if (so >= nout) break;
                    const int s  = s0 + so;
                    const int p  = s + 8;
                    const int Xp = p >> 2;
                    const int rr = p & 3;
                    float acc = 0.f, env = 0.f;
                    for (int jj = 0; jj < 4; jj++) {
                        const int tt = Xp - jj;
                        if (tt < TLO || tt > THI) continue;
                        const int n = rr + 4 * jj;
                        const float w = W16T[n];
                        acc += sm[I_OFF_P0 + (n >> 2) * PPLANE + (tt - TLO) * 4 + (n & 3)];
                        env = fmaf(w, w, env);
                    }
                    outb[so] = acc / env;
                }
            }
        }
    }
}

// ---------------------------------------------------------------------------
extern "C" void kernel_launch(void* const* d_in, const int* in_sizes, int n_in,
                              void* d_out, int out_size)
{
    (void)in_sizes; (void)n_in; (void)out_size;
    const float* mag = (const float*)d_in[0];
    float* out = (float*)d_out;
    // Maximize shared carveout; 29.6 KB/CTA -> 7 CTAs/SM.
    cudaFuncSetAttribute(glim_kernel, cudaFuncAttributePreferredSharedMemoryCarveout, 100);
    dim3 grid(NT, BATCH);
    glim_kernel<<<grid, NTHR>>>(mag, out);
}